// round 1
// baseline (speedup 1.0000x reference)
#include <cuda_runtime.h>
#include <math.h>
#include <stddef.h>

#define DIMD 1024
#define BB 2
#define LLEN 2048
#define MTOK (BB * LLEN)      // 4096 tokens
#define NHEAD 16
#define HD 64
#define ATT_SCALE 0.125f      // 64^-0.5
#define FFD (4 * DIMD)        // 4096

// ---------------- scratch (device globals; no allocations allowed) ----------
__device__ float g_nx[MTOK * DIMD];
__device__ float g_q[MTOK * DIMD];
__device__ float g_k[MTOK * DIMD];
__device__ float g_v[MTOK * DIMD];
__device__ float g_attn[MTOK * DIMD];
__device__ float g_x1[MTOK * DIMD];
__device__ float g_h[MTOK * FFD];

// ---------------- LayerNorm: one block per row of 1024 ----------------------
__global__ __launch_bounds__(256) void ln_kernel(
    const float* __restrict__ x, const float* __restrict__ g,
    const float* __restrict__ b, float* __restrict__ out)
{
    int row = blockIdx.x;
    int tid = threadIdx.x;
    float4 v = ((const float4*)(x + (size_t)row * DIMD))[tid];
    float s  = v.x + v.y + v.z + v.w;
    float sq = v.x * v.x + v.y * v.y + v.z * v.z + v.w * v.w;
    #pragma unroll
    for (int o = 16; o; o >>= 1) {
        s  += __shfl_xor_sync(0xFFFFFFFFu, s,  o);
        sq += __shfl_xor_sync(0xFFFFFFFFu, sq, o);
    }
    __shared__ float red[8], red2[8], mu_s, rs_s;
    int w = tid >> 5, ln = tid & 31;
    if (ln == 0) { red[w] = s; red2[w] = sq; }
    __syncthreads();
    if (tid == 0) {
        float ts = 0.f, tq = 0.f;
        #pragma unroll
        for (int i = 0; i < 8; i++) { ts += red[i]; tq += red2[i]; }
        float mu  = ts * (1.0f / DIMD);
        float var = tq * (1.0f / DIMD) - mu * mu;
        mu_s = mu;
        rs_s = rsqrtf(var + 1e-5f);
    }
    __syncthreads();
    float mu = mu_s, rs = rs_s;
    float4 gv = ((const float4*)g)[tid];
    float4 bv = ((const float4*)b)[tid];
    float4 o;
    o.x = (v.x - mu) * rs * gv.x + bv.x;
    o.y = (v.y - mu) * rs * gv.y + bv.y;
    o.z = (v.z - mu) * rs * gv.z + bv.z;
    o.w = (v.w - mu) * rs * gv.w + bv.w;
    ((float4*)(out + (size_t)row * DIMD))[tid] = o;
}

// ---------------- SGEMM: C[M,N] = A[M,K] * B[N,K]^T (+bias)(+gelu)(+res) ----
// 128x128 tile, BK=16, 256 threads, 8x8 fragments.
template <bool BIAS, bool GELU, bool RES>
__global__ __launch_bounds__(256) void gemm_nt(
    const float* __restrict__ A, const float* __restrict__ Bw,
    const float* __restrict__ bias, const float* __restrict__ res,
    float* __restrict__ C, int M, int N, int K)
{
    __shared__ float As[16][132];
    __shared__ float Bs[16][132];
    int m0 = blockIdx.y * 128, n0 = blockIdx.x * 128;
    int tid = threadIdx.x;
    int tx = tid & 15, ty = tid >> 4;
    float acc[8][8];
    #pragma unroll
    for (int i = 0; i < 8; i++)
        #pragma unroll
        for (int j = 0; j < 8; j++) acc[i][j] = 0.f;

    const float* Ab = A  + (size_t)m0 * K;
    const float* Bb = Bw + (size_t)n0 * K;

    for (int k0 = 0; k0 < K; k0 += 16) {
        #pragma unroll
        for (int i = 0; i < 2; i++) {
            int f = tid + i * 256;          // 0..511
            int row = f >> 2;               // 0..127
            int col = (f & 3) << 2;         // 0,4,8,12
            float4 a = *(const float4*)(Ab + (size_t)row * K + k0 + col);
            As[col + 0][row] = a.x; As[col + 1][row] = a.y;
            As[col + 2][row] = a.z; As[col + 3][row] = a.w;
            float4 bq = *(const float4*)(Bb + (size_t)row * K + k0 + col);
            Bs[col + 0][row] = bq.x; Bs[col + 1][row] = bq.y;
            Bs[col + 2][row] = bq.z; Bs[col + 3][row] = bq.w;
        }
        __syncthreads();
        #pragma unroll
        for (int k = 0; k < 16; k++) {
            float4 a0 = *(const float4*)&As[k][ty * 8];
            float4 a1 = *(const float4*)&As[k][ty * 8 + 4];
            float4 b0 = *(const float4*)&Bs[k][tx * 8];
            float4 b1 = *(const float4*)&Bs[k][tx * 8 + 4];
            float ar[8] = {a0.x, a0.y, a0.z, a0.w, a1.x, a1.y, a1.z, a1.w};
            float br[8] = {b0.x, b0.y, b0.z, b0.w, b1.x, b1.y, b1.z, b1.w};
            #pragma unroll
            for (int i = 0; i < 8; i++)
                #pragma unroll
                for (int j = 0; j < 8; j++)
                    acc[i][j] += ar[i] * br[j];
        }
        __syncthreads();
    }

    #pragma unroll
    for (int i = 0; i < 8; i++) {
        int m = m0 + ty * 8 + i;
        #pragma unroll
        for (int j = 0; j < 8; j++) {
            int n = n0 + tx * 8 + j;
            float vv = acc[i][j];
            if (BIAS) vv += bias[n];
            if (GELU) vv = 0.5f * vv * (1.f + erff(vv * 0.70710678118654752f));
            if (RES)  vv += res[(size_t)m * N + n];
            C[(size_t)m * N + n] = vv;
        }
    }
}

// ---------------- Flash attention, fp32, causal + key seq_mask --------------
// Block = (q-tile of 64 rows, head, batch). 256 threads: 4 threads per q-row.
// Each thread handles keys j = jj*4 + sub (conflict-free smem banking).
__global__ __launch_bounds__(256) void flash_kernel(
    const float* __restrict__ q, const float* __restrict__ k,
    const float* __restrict__ v, const unsigned char* __restrict__ smask,
    float* __restrict__ o)
{
    int qt  = blockIdx.x;
    int h   = blockIdx.y;
    int b   = blockIdx.z;
    int tid = threadIdx.x;
    int r   = tid >> 2;          // 0..63 q row in tile
    int sub = tid & 3;
    int q_global = qt * 64 + r;

    __shared__ float Ks[64][68];
    __shared__ float Vs[64][68];

    float qreg[64];
    {
        const float* qp = q + ((size_t)(b * LLEN + q_global)) * DIMD + h * HD;
        #pragma unroll
        for (int i = 0; i < 16; i++) {
            float4 t = *(const float4*)(qp + i * 4);
            qreg[i * 4 + 0] = t.x; qreg[i * 4 + 1] = t.y;
            qreg[i * 4 + 2] = t.z; qreg[i * 4 + 3] = t.w;
        }
    }
    float oacc[64];
    #pragma unroll
    for (int i = 0; i < 64; i++) oacc[i] = 0.f;
    float mrun = -1e30f, lrun = 0.f;

    for (int kt = 0; kt <= qt; kt++) {
        #pragma unroll
        for (int i = 0; i < 4; i++) {
            int f = tid + i * 256;       // 0..1023
            int row = f >> 4;            // 0..63
            int col = (f & 15) << 2;     // 0..60
            const float* kp = k + ((size_t)(b * LLEN + kt * 64 + row)) * DIMD + h * HD + col;
            *(float4*)&Ks[row][col] = *(const float4*)kp;
            const float* vp = v + ((size_t)(b * LLEN + kt * 64 + row)) * DIMD + h * HD + col;
            *(float4*)&Vs[row][col] = *(const float4*)vp;
        }
        __syncthreads();

        float s[16];
        #pragma unroll
        for (int jj = 0; jj < 16; jj++) s[jj] = 0.f;
        #pragma unroll 4
        for (int kk = 0; kk < 64; kk += 4) {
            #pragma unroll
            for (int jj = 0; jj < 16; jj++) {
                int j = jj * 4 + sub;
                float4 kv = *(const float4*)&Ks[j][kk];
                s[jj] += qreg[kk] * kv.x + qreg[kk + 1] * kv.y +
                         qreg[kk + 2] * kv.z + qreg[kk + 3] * kv.w;
            }
        }

        float tilemax = -1e30f;
        #pragma unroll
        for (int jj = 0; jj < 16; jj++) {
            int j  = jj * 4 + sub;
            int kj = kt * 64 + j;
            float sv = s[jj] * ATT_SCALE;
            bool masked = (kj > q_global) || (smask[b * LLEN + kj] != 0);
            sv = masked ? -10000.f : sv;
            s[jj] = sv;
            tilemax = fmaxf(tilemax, sv);
        }
        tilemax = fmaxf(tilemax, __shfl_xor_sync(0xFFFFFFFFu, tilemax, 1));
        tilemax = fmaxf(tilemax, __shfl_xor_sync(0xFFFFFFFFu, tilemax, 2));
        float mnew  = fmaxf(mrun, tilemax);
        float alpha = __expf(mrun - mnew) * (mrun > -1e29f ? 1.f : 0.f);
        if (mrun <= -1e29f && mnew <= -1e29f) alpha = 1.f;  // (never hit; safety)

        float p[16];
        float psum = 0.f;
        #pragma unroll
        for (int jj = 0; jj < 16; jj++) { p[jj] = expf(s[jj] - mnew); psum += p[jj]; }
        lrun = lrun * alpha + psum;
        #pragma unroll
        for (int c = 0; c < 64; c++) oacc[c] *= alpha;

        #pragma unroll 4
        for (int jj = 0; jj < 16; jj++) {
            int j = jj * 4 + sub;
            float pj = p[jj];
            #pragma unroll
            for (int c = 0; c < 64; c += 4) {
                float4 vv = *(const float4*)&Vs[j][c];
                oacc[c + 0] += pj * vv.x; oacc[c + 1] += pj * vv.y;
                oacc[c + 2] += pj * vv.z; oacc[c + 3] += pj * vv.w;
            }
        }
        __syncthreads();
        mrun = mnew;
    }

    lrun += __shfl_xor_sync(0xFFFFFFFFu, lrun, 1);
    lrun += __shfl_xor_sync(0xFFFFFFFFu, lrun, 2);
    float inv = 1.f / lrun;
    #pragma unroll
    for (int c = 0; c < 64; c++) {
        float t = oacc[c];
        t += __shfl_xor_sync(0xFFFFFFFFu, t, 1);
        t += __shfl_xor_sync(0xFFFFFFFFu, t, 2);
        oacc[c] = t * inv;
    }
    float* op = o + ((size_t)(b * LLEN + q_global)) * DIMD + h * HD;
    #pragma unroll
    for (int i = 0; i < 4; i++) {
        int c = sub * 16 + i * 4;
        float4 t = make_float4(oacc[c], oacc[c + 1], oacc[c + 2], oacc[c + 3]);
        *(float4*)(op + c) = t;
    }
}

// ---------------- driver ----------------------------------------------------
extern "C" void kernel_launch(void* const* d_in, const int* in_sizes, int n_in,
                              void* d_out, int out_size)
{
    const float* x            = (const float*)d_in[0];
    const unsigned char* sm   = (const unsigned char*)d_in[1];
    const float* wq           = (const float*)d_in[2];
    const float* wk           = (const float*)d_in[3];
    const float* wv           = (const float*)d_in[4];
    const float* wo           = (const float*)d_in[5];
    const float* g1           = (const float*)d_in[6];
    const float* b1           = (const float*)d_in[7];
    const float* g2           = (const float*)d_in[8];
    const float* b2           = (const float*)d_in[9];
    const float* w_mlp1       = (const float*)d_in[10];
    const float* b_mlp1       = (const float*)d_in[11];
    const float* w_mlp2       = (const float*)d_in[12];
    const float* b_mlp2       = (const float*)d_in[13];
    float* out = (float*)d_out;

    float *nx, *qb, *kb, *vb, *attn, *x1, *hb;
    cudaGetSymbolAddress((void**)&nx,   g_nx);
    cudaGetSymbolAddress((void**)&qb,   g_q);
    cudaGetSymbolAddress((void**)&kb,   g_k);
    cudaGetSymbolAddress((void**)&vb,   g_v);
    cudaGetSymbolAddress((void**)&attn, g_attn);
    cudaGetSymbolAddress((void**)&x1,   g_x1);
    cudaGetSymbolAddress((void**)&hb,   g_h);

    dim3 blk(256);
    dim3 gD(DIMD / 128, MTOK / 128);   // N=1024
    dim3 gF(FFD  / 128, MTOK / 128);   // N=4096

    // 1. nx = LN(x; g1,b1)
    ln_kernel<<<MTOK, blk>>>(x, g1, b1, nx);
    // 2-4. q,k,v = nx @ w{q,k,v}^T
    gemm_nt<false, false, false><<<gD, blk>>>(nx, wq, nullptr, nullptr, qb, MTOK, DIMD, DIMD);
    gemm_nt<false, false, false><<<gD, blk>>>(nx, wk, nullptr, nullptr, kb, MTOK, DIMD, DIMD);
    gemm_nt<false, false, false><<<gD, blk>>>(nx, wv, nullptr, nullptr, vb, MTOK, DIMD, DIMD);
    // 5. attn = causal softmax(q k^T * scale) v   (layout [b,l,h,d] == [M,D])
    flash_kernel<<<dim3(LLEN / 64, NHEAD, BB), blk>>>(qb, kb, vb, sm, attn);
    // 6. x1 = x + attn @ wo^T
    gemm_nt<false, false, true><<<gD, blk>>>(attn, wo, nullptr, x, x1, MTOK, DIMD, DIMD);
    // 7. nx = LN(x1; g2,b2)
    ln_kernel<<<MTOK, blk>>>(x1, g2, b2, nx);
    // 8. h = gelu(nx @ w_mlp1^T + b_mlp1)
    gemm_nt<true, true, false><<<gF, blk>>>(nx, w_mlp1, b_mlp1, nullptr, hb, MTOK, FFD, DIMD);
    // 9. out = x1 + h @ w_mlp2^T + b_mlp2
    gemm_nt<true, false, true><<<gD, blk>>>(hb, w_mlp2, b_mlp2, x1, out, MTOK, DIMD, FFD);
}

// round 3
// speedup vs baseline: 2.3849x; 2.3849x over previous
#include <cuda_runtime.h>
#include <cuda_bf16.h>
#include <math.h>
#include <stddef.h>
#include <stdint.h>

#define DIMD 1024
#define BB 2
#define LLEN 2048
#define MTOK 4096
#define NHEAD 16
#define HD 64
#define ATT_SCALE 0.125f
#define FFD 4096
#define QKVN 3072

typedef __nv_bfloat16 bf16;

// ---------------- scratch (device globals; no allocations allowed) ----------
__device__ bf16  g_nx_hi[MTOK * DIMD],  g_nx_lo[MTOK * DIMD];
__device__ bf16  g_wqkv_hi[QKVN * DIMD], g_wqkv_lo[QKVN * DIMD];
__device__ bf16  g_wo_hi[DIMD * DIMD],  g_wo_lo[DIMD * DIMD];
__device__ bf16  g_w1_hi[FFD * DIMD],   g_w1_lo[FFD * DIMD];
__device__ bf16  g_w2_hi[DIMD * FFD],   g_w2_lo[DIMD * FFD];
__device__ float g_qkv[MTOK * QKVN];
__device__ bf16  g_attn_hi[MTOK * DIMD], g_attn_lo[MTOK * DIMD];
__device__ float g_x1[MTOK * DIMD];
__device__ bf16  g_h_hi[(size_t)MTOK * FFD], g_h_lo[(size_t)MTOK * FFD];

// ---------------- helpers -----------------------------------------------------
__device__ __forceinline__ uint32_t cvta_s(const void* p) {
    return (uint32_t)__cvta_generic_to_shared(p);
}
__device__ __forceinline__ void cp16(uint32_t dst, const void* src) {
    asm volatile("cp.async.cg.shared.global [%0], [%1], 16;" :: "r"(dst), "l"(src) : "memory");
}
__device__ __forceinline__ void ldm_x4(uint32_t addr, uint32_t& r0, uint32_t& r1,
                                       uint32_t& r2, uint32_t& r3) {
    asm volatile("ldmatrix.sync.aligned.m8n8.x4.shared.b16 {%0,%1,%2,%3}, [%4];"
                 : "=r"(r0), "=r"(r1), "=r"(r2), "=r"(r3) : "r"(addr));
}
__device__ __forceinline__ void mma_bf16(float& d0, float& d1, float& d2, float& d3,
                                         uint32_t a0, uint32_t a1, uint32_t a2, uint32_t a3,
                                         uint32_t b0, uint32_t b1) {
    asm volatile(
        "mma.sync.aligned.m16n8k16.row.col.f32.bf16.bf16.f32 "
        "{%0,%1,%2,%3}, {%4,%5,%6,%7}, {%8,%9}, {%0,%1,%2,%3};"
        : "+f"(d0), "+f"(d1), "+f"(d2), "+f"(d3)
        : "r"(a0), "r"(a1), "r"(a2), "r"(a3), "r"(b0), "r"(b1));
}

// ---------------- conversion: fp32 -> (hi, lo) bf16 -------------------------
__global__ __launch_bounds__(256) void convert_kernel(
    const float* __restrict__ w, bf16* __restrict__ hi, bf16* __restrict__ lo, int n)
{
    int i = (blockIdx.x * 256 + threadIdx.x) * 4;
    if (i >= n) return;
    float4 v = *(const float4*)(w + i);
    float vv[4] = {v.x, v.y, v.z, v.w};
    bf16 h4[4], l4[4];
    #pragma unroll
    for (int j = 0; j < 4; j++) {
        bf16 h = __float2bfloat16(vv[j]);
        h4[j] = h;
        l4[j] = __float2bfloat16(vv[j] - __bfloat162float(h));
    }
    *(uint2*)(hi + i) = *(uint2*)h4;
    *(uint2*)(lo + i) = *(uint2*)l4;
}

// ---------------- LayerNorm -> (hi, lo) bf16 --------------------------------
__global__ __launch_bounds__(256) void ln_kernel(
    const float* __restrict__ x, const float* __restrict__ g,
    const float* __restrict__ b, bf16* __restrict__ ohi, bf16* __restrict__ olo)
{
    int row = blockIdx.x;
    int tid = threadIdx.x;
    float4 v = ((const float4*)(x + (size_t)row * DIMD))[tid];
    float s  = v.x + v.y + v.z + v.w;
    float sq = v.x * v.x + v.y * v.y + v.z * v.z + v.w * v.w;
    #pragma unroll
    for (int o = 16; o; o >>= 1) {
        s  += __shfl_xor_sync(0xFFFFFFFFu, s,  o);
        sq += __shfl_xor_sync(0xFFFFFFFFu, sq, o);
    }
    __shared__ float red[8], red2[8], mu_s, rs_s;
    int w = tid >> 5, ln = tid & 31;
    if (ln == 0) { red[w] = s; red2[w] = sq; }
    __syncthreads();
    if (tid == 0) {
        float ts = 0.f, tq = 0.f;
        #pragma unroll
        for (int i = 0; i < 8; i++) { ts += red[i]; tq += red2[i]; }
        float mu  = ts * (1.0f / DIMD);
        float var = tq * (1.0f / DIMD) - mu * mu;
        mu_s = mu;
        rs_s = rsqrtf(var + 1e-5f);
    }
    __syncthreads();
    float mu = mu_s, rs = rs_s;
    float4 gv = ((const float4*)g)[tid];
    float4 bv = ((const float4*)b)[tid];
    float o4[4];
    o4[0] = (v.x - mu) * rs * gv.x + bv.x;
    o4[1] = (v.y - mu) * rs * gv.y + bv.y;
    o4[2] = (v.z - mu) * rs * gv.z + bv.z;
    o4[3] = (v.w - mu) * rs * gv.w + bv.w;
    bf16 h4[4], l4[4];
    #pragma unroll
    for (int j = 0; j < 4; j++) {
        bf16 h = __float2bfloat16(o4[j]);
        h4[j] = h;
        l4[j] = __float2bfloat16(o4[j] - __bfloat162float(h));
    }
    size_t base = (size_t)row * DIMD + tid * 4;
    *(uint2*)(ohi + base) = *(uint2*)h4;
    *(uint2*)(olo + base) = *(uint2*)l4;
}

// ---------------- HMMA split-bf16 GEMM ---------------------------------------
// C[M,N] = A[M,K]*B[N,K]^T via virtual K'=3K: [Ahi|Alo|Ahi] x [Bhi|Bhi|Blo].
// 128x128 CTA tile, BK=32, 8 warps (4M x 2N -> 32x64 warp tile), 3-stage cp.async.
// smem row stride 40 bf16 (80B): conflict-free ldmatrix phases.
// EPI: 0=f32  1=f32+res  2=f32+bias+res  3=bias+gelu -> (hi,lo) bf16
#define SSTRIDE 40
#define TILE_BYTES (128 * SSTRIDE * 2)     // 10240
#define STAGE_BYTES (2 * TILE_BYTES)       // A+B per stage
#define NSTAGE 3
#define SMEM_DYN (NSTAGE * STAGE_BYTES)    // 61440

template <int EPI>
__global__ __launch_bounds__(256) void gemm_tc(
    const bf16* __restrict__ Ahi, const bf16* __restrict__ Alo,
    const bf16* __restrict__ Bhi, const bf16* __restrict__ Blo,
    const float* __restrict__ bias, const float* __restrict__ res,
    float* __restrict__ Cf, bf16* __restrict__ Chi, bf16* __restrict__ Clo,
    int M, int N, int K)
{
    extern __shared__ __align__(128) char smem[];
    uint32_t sbase = cvta_s(smem);
    int tid  = threadIdx.x;
    int lane = tid & 31;
    int w    = tid >> 5;
    int warpM = w & 3, warpN = w >> 2;
    int m0 = blockIdx.y * 128, n0 = blockIdx.x * 128;

    const int kcpp = K >> 5;       // 32-wide chunks per phase
    const int C = 3 * kcpp;

    float acc[2][8][4];
    #pragma unroll
    for (int i = 0; i < 2; i++)
        #pragma unroll
        for (int j = 0; j < 8; j++)
            #pragma unroll
            for (int t = 0; t < 4; t++) acc[i][j][t] = 0.f;

    // chunk loader: 512 slots per tile, 2 per thread per tile
    auto load_chunk = [&](int c, int stage) {
        int phase = c / kcpp;
        int k0 = (c - phase * kcpp) << 5;
        const bf16* Ap = (phase == 1) ? Alo : Ahi;
        const bf16* Bp = (phase == 2) ? Blo : Bhi;
        uint32_t abuf = sbase + stage * STAGE_BYTES;
        uint32_t bbuf = abuf + TILE_BYTES;
        #pragma unroll
        for (int i = 0; i < 2; i++) {
            int idx = tid + i * 256;          // 0..511
            int row = idx >> 2;               // 0..127
            int cg  = idx & 3;                // 16B group
            uint32_t doff = row * (SSTRIDE * 2) + cg * 16;
            cp16(abuf + doff, Ap + (size_t)(m0 + row) * K + k0 + cg * 8);
            cp16(bbuf + doff, Bp + (size_t)(n0 + row) * K + k0 + cg * 8);
        }
        asm volatile("cp.async.commit_group;");
    };

    load_chunk(0, 0);
    load_chunk(1, 1);
    load_chunk(2, 2);

    // ldmatrix lane addressing (row-major m16k16 / n16k16 tiles)
    int lrow = lane & 15;            // row within 16
    int lcol = (lane >> 4) << 3;     // 0 or 8 elems

    for (int c = 0; c < C; c++) {
        asm volatile("cp.async.wait_group 2;" ::: "memory");
        __syncthreads();
        int stage = c - (c / NSTAGE) * NSTAGE;
        uint32_t abuf = sbase + stage * STAGE_BYTES;
        uint32_t bbuf = abuf + TILE_BYTES;

        #pragma unroll
        for (int ks = 0; ks < 2; ks++) {
            int kk = ks * 16;
            uint32_t a[2][4];
            #pragma unroll
            for (int mi = 0; mi < 2; mi++) {
                int r = warpM * 32 + mi * 16 + lrow;
                uint32_t addr = abuf + (r * SSTRIDE + kk + lcol) * 2;
                ldm_x4(addr, a[mi][0], a[mi][1], a[mi][2], a[mi][3]);
            }
            uint32_t bfr[8][2];
            #pragma unroll
            for (int nj = 0; nj < 4; nj++) {
                int r = warpN * 64 + nj * 16 + lrow;
                uint32_t addr = bbuf + (r * SSTRIDE + kk + lcol) * 2;
                uint32_t b0, b1, b2, b3;
                ldm_x4(addr, b0, b1, b2, b3);
                bfr[nj * 2 + 0][0] = b0; bfr[nj * 2 + 0][1] = b2;
                bfr[nj * 2 + 1][0] = b1; bfr[nj * 2 + 1][1] = b3;
            }
            #pragma unroll
            for (int mi = 0; mi < 2; mi++)
                #pragma unroll
                for (int nt = 0; nt < 8; nt++)
                    mma_bf16(acc[mi][nt][0], acc[mi][nt][1], acc[mi][nt][2], acc[mi][nt][3],
                             a[mi][0], a[mi][1], a[mi][2], a[mi][3],
                             bfr[nt][0], bfr[nt][1]);
        }
        __syncthreads();
        if (c + NSTAGE < C) load_chunk(c + NSTAGE, stage);
    }

    // ---------------- epilogue ----------------
    int rbase = m0 + warpM * 32 + (lane >> 2);
    int cbase = n0 + warpN * 64 + (lane & 3) * 2;

    #pragma unroll
    for (int mi = 0; mi < 2; mi++) {
        #pragma unroll
        for (int half = 0; half < 2; half++) {       // j pair: rows +0 / +8
            int row = rbase + mi * 16 + half * 8;
            size_t gr = (size_t)row * N;
            #pragma unroll
            for (int nt = 0; nt < 8; nt++) {
                int col = cbase + nt * 8;
                float v0 = acc[mi][nt][half * 2 + 0];
                float v1 = acc[mi][nt][half * 2 + 1];
                if (EPI == 2 || EPI == 3) { v0 += bias[col]; v1 += bias[col + 1]; }
                if (EPI == 3) {
                    v0 = 0.5f * v0 * (1.f + erff(v0 * 0.70710678118654752f));
                    v1 = 0.5f * v1 * (1.f + erff(v1 * 0.70710678118654752f));
                    bf16 h0 = __float2bfloat16(v0);
                    bf16 h1 = __float2bfloat16(v1);
                    bf16 l0 = __float2bfloat16(v0 - __bfloat162float(h0));
                    bf16 l1 = __float2bfloat16(v1 - __bfloat162float(h1));
                    bf16 hp[2] = {h0, h1}, lp[2] = {l0, l1};
                    *(uint32_t*)(Chi + gr + col) = *(uint32_t*)hp;
                    *(uint32_t*)(Clo + gr + col) = *(uint32_t*)lp;
                } else {
                    if (EPI == 1 || EPI == 2) {
                        float2 rr = *(const float2*)(res + gr + col);
                        v0 += rr.x; v1 += rr.y;
                    }
                    float2 o = make_float2(v0, v1);
                    *(float2*)(Cf + gr + col) = o;
                }
            }
        }
    }
}

// ---------------- Flash attention (fp32) -> attn (hi,lo) bf16 ----------------
__global__ __launch_bounds__(256) void flash_kernel(
    const float* __restrict__ qkv, const unsigned char* __restrict__ smask,
    bf16* __restrict__ ohi, bf16* __restrict__ olo)
{
    int qt  = blockIdx.x;
    int h   = blockIdx.y;
    int b   = blockIdx.z;
    int tid = threadIdx.x;
    int r   = tid >> 2;
    int sub = tid & 3;
    int q_global = qt * 64 + r;

    __shared__ float Ks[64][68];
    __shared__ float Vs[64][68];

    float qreg[64];
    {
        const float* qp = qkv + (size_t)(b * LLEN + q_global) * QKVN + h * HD;
        #pragma unroll
        for (int i = 0; i < 16; i++) {
            float4 t = *(const float4*)(qp + i * 4);
            qreg[i * 4 + 0] = t.x; qreg[i * 4 + 1] = t.y;
            qreg[i * 4 + 2] = t.z; qreg[i * 4 + 3] = t.w;
        }
    }
    float oacc[64];
    #pragma unroll
    for (int i = 0; i < 64; i++) oacc[i] = 0.f;
    float mrun = -1e30f, lrun = 0.f;

    for (int kt = 0; kt <= qt; kt++) {
        #pragma unroll
        for (int i = 0; i < 4; i++) {
            int f = tid + i * 256;
            int row = f >> 4;
            int col = (f & 15) << 2;
            const float* kp = qkv + (size_t)(b * LLEN + kt * 64 + row) * QKVN + DIMD + h * HD + col;
            *(float4*)&Ks[row][col] = *(const float4*)kp;
            const float* vp = qkv + (size_t)(b * LLEN + kt * 64 + row) * QKVN + 2 * DIMD + h * HD + col;
            *(float4*)&Vs[row][col] = *(const float4*)vp;
        }
        __syncthreads();

        float s[16];
        #pragma unroll
        for (int jj = 0; jj < 16; jj++) s[jj] = 0.f;
        #pragma unroll 4
        for (int kk = 0; kk < 64; kk += 4) {
            #pragma unroll
            for (int jj = 0; jj < 16; jj++) {
                int j = jj * 4 + sub;
                float4 kv = *(const float4*)&Ks[j][kk];
                s[jj] += qreg[kk] * kv.x + qreg[kk + 1] * kv.y +
                         qreg[kk + 2] * kv.z + qreg[kk + 3] * kv.w;
            }
        }

        float tilemax = -1e30f;
        #pragma unroll
        for (int jj = 0; jj < 16; jj++) {
            int j  = jj * 4 + sub;
            int kj = kt * 64 + j;
            float sv = s[jj] * ATT_SCALE;
            bool masked = (kj > q_global) || (smask[b * LLEN + kj] != 0);
            sv = masked ? -10000.f : sv;
            s[jj] = sv;
            tilemax = fmaxf(tilemax, sv);
        }
        tilemax = fmaxf(tilemax, __shfl_xor_sync(0xFFFFFFFFu, tilemax, 1));
        tilemax = fmaxf(tilemax, __shfl_xor_sync(0xFFFFFFFFu, tilemax, 2));
        float mnew  = fmaxf(mrun, tilemax);
        float alpha = __expf(mrun - mnew) * (mrun > -1e29f ? 1.f : 0.f);
        if (mrun <= -1e29f && mnew <= -1e29f) alpha = 1.f;

        float p[16];
        float psum = 0.f;
        #pragma unroll
        for (int jj = 0; jj < 16; jj++) { p[jj] = expf(s[jj] - mnew); psum += p[jj]; }
        lrun = lrun * alpha + psum;
        #pragma unroll
        for (int c = 0; c < 64; c++) oacc[c] *= alpha;

        #pragma unroll 4
        for (int jj = 0; jj < 16; jj++) {
            int j = jj * 4 + sub;
            float pj = p[jj];
            #pragma unroll
            for (int c = 0; c < 64; c += 4) {
                float4 vv = *(const float4*)&Vs[j][c];
                oacc[c + 0] += pj * vv.x; oacc[c + 1] += pj * vv.y;
                oacc[c + 2] += pj * vv.z; oacc[c + 3] += pj * vv.w;
            }
        }
        __syncthreads();
        mrun = mnew;
    }

    lrun += __shfl_xor_sync(0xFFFFFFFFu, lrun, 1);
    lrun += __shfl_xor_sync(0xFFFFFFFFu, lrun, 2);
    float inv = 1.f / lrun;
    #pragma unroll
    for (int c = 0; c < 64; c++) {
        float t = oacc[c];
        t += __shfl_xor_sync(0xFFFFFFFFu, t, 1);
        t += __shfl_xor_sync(0xFFFFFFFFu, t, 2);
        oacc[c] = t * inv;
    }
    size_t obase = (size_t)(b * LLEN + q_global) * DIMD + h * HD + sub * 16;
    bf16 h16[16], l16[16];
    #pragma unroll
    for (int i = 0; i < 16; i++) {
        float v = oacc[sub * 16 + i];
        bf16 hh = __float2bfloat16(v);
        h16[i] = hh;
        l16[i] = __float2bfloat16(v - __bfloat162float(hh));
    }
    *(uint4*)(ohi + obase)     = *(uint4*)(h16);
    *(uint4*)(ohi + obase + 8) = *(uint4*)(h16 + 8);
    *(uint4*)(olo + obase)     = *(uint4*)(l16);
    *(uint4*)(olo + obase + 8) = *(uint4*)(l16 + 8);
}

// ---------------- driver -----------------------------------------------------
extern "C" void kernel_launch(void* const* d_in, const int* in_sizes, int n_in,
                              void* d_out, int out_size)
{
    const float* x          = (const float*)d_in[0];
    const unsigned char* sm = (const unsigned char*)d_in[1];
    const float* wq         = (const float*)d_in[2];
    const float* wk         = (const float*)d_in[3];
    const float* wv         = (const float*)d_in[4];
    const float* wo         = (const float*)d_in[5];
    const float* g1         = (const float*)d_in[6];
    const float* b1         = (const float*)d_in[7];
    const float* g2         = (const float*)d_in[8];
    const float* b2         = (const float*)d_in[9];
    const float* w_mlp1     = (const float*)d_in[10];
    const float* b_mlp1     = (const float*)d_in[11];
    const float* w_mlp2     = (const float*)d_in[12];
    const float* b_mlp2     = (const float*)d_in[13];
    float* out = (float*)d_out;

    bf16 *nxh, *nxl, *wqkvh, *wqkvl, *woh, *wol, *w1h, *w1l, *w2h, *w2l;
    bf16 *atth, *attl, *hh, *hl;
    float *qkv, *x1;
    cudaGetSymbolAddress((void**)&nxh, g_nx_hi);   cudaGetSymbolAddress((void**)&nxl, g_nx_lo);
    cudaGetSymbolAddress((void**)&wqkvh, g_wqkv_hi); cudaGetSymbolAddress((void**)&wqkvl, g_wqkv_lo);
    cudaGetSymbolAddress((void**)&woh, g_wo_hi);   cudaGetSymbolAddress((void**)&wol, g_wo_lo);
    cudaGetSymbolAddress((void**)&w1h, g_w1_hi);   cudaGetSymbolAddress((void**)&w1l, g_w1_lo);
    cudaGetSymbolAddress((void**)&w2h, g_w2_hi);   cudaGetSymbolAddress((void**)&w2l, g_w2_lo);
    cudaGetSymbolAddress((void**)&qkv, g_qkv);
    cudaGetSymbolAddress((void**)&atth, g_attn_hi); cudaGetSymbolAddress((void**)&attl, g_attn_lo);
    cudaGetSymbolAddress((void**)&x1, g_x1);
    cudaGetSymbolAddress((void**)&hh, g_h_hi);     cudaGetSymbolAddress((void**)&hl, g_h_lo);

    cudaFuncSetAttribute(gemm_tc<0>, cudaFuncAttributeMaxDynamicSharedMemorySize, SMEM_DYN);
    cudaFuncSetAttribute(gemm_tc<1>, cudaFuncAttributeMaxDynamicSharedMemorySize, SMEM_DYN);
    cudaFuncSetAttribute(gemm_tc<2>, cudaFuncAttributeMaxDynamicSharedMemorySize, SMEM_DYN);
    cudaFuncSetAttribute(gemm_tc<3>, cudaFuncAttributeMaxDynamicSharedMemorySize, SMEM_DYN);

    dim3 blk(256);
    const int DD = DIMD * DIMD;

    // weight conversions (fused qkv weight buffer)
    convert_kernel<<<DD / 1024, blk>>>(wq, wqkvh, wqkvl, DD);
    convert_kernel<<<DD / 1024, blk>>>(wk, wqkvh + DD, wqkvl + DD, DD);
    convert_kernel<<<DD / 1024, blk>>>(wv, wqkvh + 2 * DD, wqkvl + 2 * DD, DD);
    convert_kernel<<<DD / 1024, blk>>>(wo, woh, wol, DD);
    convert_kernel<<<(FFD * DIMD) / 1024, blk>>>(w_mlp1, w1h, w1l, FFD * DIMD);
    convert_kernel<<<(DIMD * FFD) / 1024, blk>>>(w_mlp2, w2h, w2l, DIMD * FFD);

    // 1. nx = LN(x; g1,b1) -> hi/lo
    ln_kernel<<<MTOK, blk>>>(x, g1, b1, nxh, nxl);
    // 2. qkv = nx @ wqkv^T  (fp32)
    gemm_tc<0><<<dim3(QKVN / 128, MTOK / 128), blk, SMEM_DYN>>>(
        nxh, nxl, wqkvh, wqkvl, nullptr, nullptr, qkv, nullptr, nullptr,
        MTOK, QKVN, DIMD);
    // 3. attn = flash(qkv) -> hi/lo
    flash_kernel<<<dim3(LLEN / 64, NHEAD, BB), blk>>>(qkv, sm, atth, attl);
    // 4. x1 = x + attn @ wo^T
    gemm_tc<1><<<dim3(DIMD / 128, MTOK / 128), blk, SMEM_DYN>>>(
        atth, attl, woh, wol, nullptr, x, x1, nullptr, nullptr,
        MTOK, DIMD, DIMD);
    // 5. nx = LN(x1; g2,b2) -> hi/lo
    ln_kernel<<<MTOK, blk>>>(x1, g2, b2, nxh, nxl);
    // 6. h = gelu(nx @ w1^T + b1) -> hi/lo
    gemm_tc<3><<<dim3(FFD / 128, MTOK / 128), blk, SMEM_DYN>>>(
        nxh, nxl, w1h, w1l, b_mlp1, nullptr, nullptr, hh, hl,
        MTOK, FFD, DIMD);
    // 7. out = x1 + h @ w2^T + b2
    gemm_tc<2><<<dim3(DIMD / 128, MTOK / 128), blk, SMEM_DYN>>>(
        hh, hl, w2h, w2l, b_mlp2, x1, out, nullptr, nullptr,
        MTOK, DIMD, FFD);
}

// round 4
// speedup vs baseline: 4.5655x; 1.9144x over previous
#include <cuda_runtime.h>
#include <cuda_bf16.h>
#include <math.h>
#include <stddef.h>
#include <stdint.h>

#define DIMD 1024
#define BB 2
#define LLEN 2048
#define MTOK 4096
#define NHEAD 16
#define HD 64
#define FFD 4096
#define QKVN 3072

typedef __nv_bfloat16 bf16;

// ---------------- scratch (device globals; no allocations allowed) ----------
__device__ bf16  g_nx_hi[MTOK * DIMD],  g_nx_lo[MTOK * DIMD];
__device__ bf16  g_wqkv_hi[QKVN * DIMD], g_wqkv_lo[QKVN * DIMD];
__device__ bf16  g_wo_hi[DIMD * DIMD],  g_wo_lo[DIMD * DIMD];
__device__ bf16  g_w1_hi[FFD * DIMD],   g_w1_lo[FFD * DIMD];
__device__ bf16  g_w2_hi[DIMD * FFD],   g_w2_lo[DIMD * FFD];
__device__ bf16  g_qkv_hi[(size_t)MTOK * QKVN], g_qkv_lo[(size_t)MTOK * QKVN];
__device__ bf16  g_attn_hi[MTOK * DIMD], g_attn_lo[MTOK * DIMD];
__device__ float g_x1[MTOK * DIMD];
__device__ bf16  g_h_hi[(size_t)MTOK * FFD], g_h_lo[(size_t)MTOK * FFD];

// ---------------- helpers -----------------------------------------------------
__device__ __forceinline__ uint32_t cvta_s(const void* p) {
    return (uint32_t)__cvta_generic_to_shared(p);
}
__device__ __forceinline__ void cp16(uint32_t dst, const void* src) {
    asm volatile("cp.async.cg.shared.global [%0], [%1], 16;" :: "r"(dst), "l"(src) : "memory");
}
__device__ __forceinline__ void ldm_x4(uint32_t addr, uint32_t& r0, uint32_t& r1,
                                       uint32_t& r2, uint32_t& r3) {
    asm volatile("ldmatrix.sync.aligned.m8n8.x4.shared.b16 {%0,%1,%2,%3}, [%4];"
                 : "=r"(r0), "=r"(r1), "=r"(r2), "=r"(r3) : "r"(addr));
}
__device__ __forceinline__ void ldm_x4_t(uint32_t addr, uint32_t& r0, uint32_t& r1,
                                         uint32_t& r2, uint32_t& r3) {
    asm volatile("ldmatrix.sync.aligned.m8n8.x4.trans.shared.b16 {%0,%1,%2,%3}, [%4];"
                 : "=r"(r0), "=r"(r1), "=r"(r2), "=r"(r3) : "r"(addr));
}
__device__ __forceinline__ void mma_bf16(float& d0, float& d1, float& d2, float& d3,
                                         uint32_t a0, uint32_t a1, uint32_t a2, uint32_t a3,
                                         uint32_t b0, uint32_t b1) {
    asm volatile(
        "mma.sync.aligned.m16n8k16.row.col.f32.bf16.bf16.f32 "
        "{%0,%1,%2,%3}, {%4,%5,%6,%7}, {%8,%9}, {%0,%1,%2,%3};"
        : "+f"(d0), "+f"(d1), "+f"(d2), "+f"(d3)
        : "r"(a0), "r"(a1), "r"(a2), "r"(a3), "r"(b0), "r"(b1));
}
__device__ __forceinline__ uint32_t pack2bf(bf16 lo, bf16 hi) {
    return (uint32_t)__bfloat16_as_ushort(lo) | ((uint32_t)__bfloat16_as_ushort(hi) << 16);
}

// ---------------- conversion: fp32 -> (hi, lo) bf16 -------------------------
__global__ __launch_bounds__(256) void convert_kernel(
    const float* __restrict__ w, bf16* __restrict__ hi, bf16* __restrict__ lo, int n)
{
    int i = (blockIdx.x * 256 + threadIdx.x) * 4;
    if (i >= n) return;
    float4 v = *(const float4*)(w + i);
    float vv[4] = {v.x, v.y, v.z, v.w};
    bf16 h4[4], l4[4];
    #pragma unroll
    for (int j = 0; j < 4; j++) {
        bf16 h = __float2bfloat16(vv[j]);
        h4[j] = h;
        l4[j] = __float2bfloat16(vv[j] - __bfloat162float(h));
    }
    *(uint2*)(hi + i) = *(uint2*)h4;
    *(uint2*)(lo + i) = *(uint2*)l4;
}

// ---------------- LayerNorm -> (hi, lo) bf16 --------------------------------
__global__ __launch_bounds__(256) void ln_kernel(
    const float* __restrict__ x, const float* __restrict__ g,
    const float* __restrict__ b, bf16* __restrict__ ohi, bf16* __restrict__ olo)
{
    int row = blockIdx.x;
    int tid = threadIdx.x;
    float4 v = ((const float4*)(x + (size_t)row * DIMD))[tid];
    float s  = v.x + v.y + v.z + v.w;
    float sq = v.x * v.x + v.y * v.y + v.z * v.z + v.w * v.w;
    #pragma unroll
    for (int o = 16; o; o >>= 1) {
        s  += __shfl_xor_sync(0xFFFFFFFFu, s,  o);
        sq += __shfl_xor_sync(0xFFFFFFFFu, sq, o);
    }
    __shared__ float red[8], red2[8], mu_s, rs_s;
    int w = tid >> 5, ln = tid & 31;
    if (ln == 0) { red[w] = s; red2[w] = sq; }
    __syncthreads();
    if (tid == 0) {
        float ts = 0.f, tq = 0.f;
        #pragma unroll
        for (int i = 0; i < 8; i++) { ts += red[i]; tq += red2[i]; }
        float mu  = ts * (1.0f / DIMD);
        float var = tq * (1.0f / DIMD) - mu * mu;
        mu_s = mu;
        rs_s = rsqrtf(var + 1e-5f);
    }
    __syncthreads();
    float mu = mu_s, rs = rs_s;
    float4 gv = ((const float4*)g)[tid];
    float4 bv = ((const float4*)b)[tid];
    float o4[4];
    o4[0] = (v.x - mu) * rs * gv.x + bv.x;
    o4[1] = (v.y - mu) * rs * gv.y + bv.y;
    o4[2] = (v.z - mu) * rs * gv.z + bv.z;
    o4[3] = (v.w - mu) * rs * gv.w + bv.w;
    bf16 h4[4], l4[4];
    #pragma unroll
    for (int j = 0; j < 4; j++) {
        bf16 h = __float2bfloat16(o4[j]);
        h4[j] = h;
        l4[j] = __float2bfloat16(o4[j] - __bfloat162float(h));
    }
    size_t base = (size_t)row * DIMD + tid * 4;
    *(uint2*)(ohi + base) = *(uint2*)h4;
    *(uint2*)(olo + base) = *(uint2*)l4;
}

// ---------------- HMMA split-bf16 GEMM ---------------------------------------
// EPI: 0=f32  1=f32+res  2=f32+bias+res  3=bias+gelu->(hi,lo)  4=(hi,lo)
#define SSTRIDE 40
#define TILE_BYTES (128 * SSTRIDE * 2)
#define STAGE_BYTES (2 * TILE_BYTES)
#define NSTAGE 3
#define SMEM_DYN (NSTAGE * STAGE_BYTES)

template <int EPI>
__global__ __launch_bounds__(256) void gemm_tc(
    const bf16* __restrict__ Ahi, const bf16* __restrict__ Alo,
    const bf16* __restrict__ Bhi, const bf16* __restrict__ Blo,
    const float* __restrict__ bias, const float* __restrict__ res,
    float* __restrict__ Cf, bf16* __restrict__ Chi, bf16* __restrict__ Clo,
    int M, int N, int K)
{
    extern __shared__ __align__(128) char smem[];
    uint32_t sbase = cvta_s(smem);
    int tid  = threadIdx.x;
    int lane = tid & 31;
    int w    = tid >> 5;
    int warpM = w & 3, warpN = w >> 2;
    int m0 = blockIdx.y * 128, n0 = blockIdx.x * 128;

    const int kcpp = K >> 5;
    const int C = 3 * kcpp;

    float acc[2][8][4];
    #pragma unroll
    for (int i = 0; i < 2; i++)
        #pragma unroll
        for (int j = 0; j < 8; j++)
            #pragma unroll
            for (int t = 0; t < 4; t++) acc[i][j][t] = 0.f;

    auto load_chunk = [&](int c, int stage) {
        int phase = c / kcpp;
        int k0 = (c - phase * kcpp) << 5;
        const bf16* Ap = (phase == 1) ? Alo : Ahi;
        const bf16* Bp = (phase == 2) ? Blo : Bhi;
        uint32_t abuf = sbase + stage * STAGE_BYTES;
        uint32_t bbuf = abuf + TILE_BYTES;
        #pragma unroll
        for (int i = 0; i < 2; i++) {
            int idx = tid + i * 256;
            int row = idx >> 2;
            int cg  = idx & 3;
            uint32_t doff = row * (SSTRIDE * 2) + cg * 16;
            cp16(abuf + doff, Ap + (size_t)(m0 + row) * K + k0 + cg * 8);
            cp16(bbuf + doff, Bp + (size_t)(n0 + row) * K + k0 + cg * 8);
        }
        asm volatile("cp.async.commit_group;");
    };

    load_chunk(0, 0);
    load_chunk(1, 1);
    load_chunk(2, 2);

    int lrow = lane & 15;
    int lcol = (lane >> 4) << 3;

    for (int c = 0; c < C; c++) {
        asm volatile("cp.async.wait_group 2;" ::: "memory");
        __syncthreads();
        int stage = c - (c / NSTAGE) * NSTAGE;
        uint32_t abuf = sbase + stage * STAGE_BYTES;
        uint32_t bbuf = abuf + TILE_BYTES;

        #pragma unroll
        for (int ks = 0; ks < 2; ks++) {
            int kk = ks * 16;
            uint32_t a[2][4];
            #pragma unroll
            for (int mi = 0; mi < 2; mi++) {
                int r = warpM * 32 + mi * 16 + lrow;
                uint32_t addr = abuf + (r * SSTRIDE + kk + lcol) * 2;
                ldm_x4(addr, a[mi][0], a[mi][1], a[mi][2], a[mi][3]);
            }
            uint32_t bfr[8][2];
            #pragma unroll
            for (int nj = 0; nj < 4; nj++) {
                int r = warpN * 64 + nj * 16 + lrow;
                uint32_t addr = bbuf + (r * SSTRIDE + kk + lcol) * 2;
                uint32_t b0, b1, b2, b3;
                ldm_x4(addr, b0, b1, b2, b3);
                bfr[nj * 2 + 0][0] = b0; bfr[nj * 2 + 0][1] = b2;
                bfr[nj * 2 + 1][0] = b1; bfr[nj * 2 + 1][1] = b3;
            }
            #pragma unroll
            for (int mi = 0; mi < 2; mi++)
                #pragma unroll
                for (int nt = 0; nt < 8; nt++)
                    mma_bf16(acc[mi][nt][0], acc[mi][nt][1], acc[mi][nt][2], acc[mi][nt][3],
                             a[mi][0], a[mi][1], a[mi][2], a[mi][3],
                             bfr[nt][0], bfr[nt][1]);
        }
        __syncthreads();
        if (c + NSTAGE < C) load_chunk(c + NSTAGE, stage);
    }

    int rbase = m0 + warpM * 32 + (lane >> 2);
    int cbase = n0 + warpN * 64 + (lane & 3) * 2;

    #pragma unroll
    for (int mi = 0; mi < 2; mi++) {
        #pragma unroll
        for (int half = 0; half < 2; half++) {
            int row = rbase + mi * 16 + half * 8;
            size_t gr = (size_t)row * N;
            #pragma unroll
            for (int nt = 0; nt < 8; nt++) {
                int col = cbase + nt * 8;
                float v0 = acc[mi][nt][half * 2 + 0];
                float v1 = acc[mi][nt][half * 2 + 1];
                if (EPI == 2 || EPI == 3) { v0 += bias[col]; v1 += bias[col + 1]; }
                if (EPI == 3 || EPI == 4) {
                    if (EPI == 3) {
                        v0 = 0.5f * v0 * (1.f + erff(v0 * 0.70710678118654752f));
                        v1 = 0.5f * v1 * (1.f + erff(v1 * 0.70710678118654752f));
                    }
                    bf16 h0 = __float2bfloat16(v0);
                    bf16 h1 = __float2bfloat16(v1);
                    bf16 l0 = __float2bfloat16(v0 - __bfloat162float(h0));
                    bf16 l1 = __float2bfloat16(v1 - __bfloat162float(h1));
                    *(uint32_t*)(Chi + gr + col) = pack2bf(h0, h1);
                    *(uint32_t*)(Clo + gr + col) = pack2bf(l0, l1);
                } else {
                    if (EPI == 1 || EPI == 2) {
                        float2 rr = *(const float2*)(res + gr + col);
                        v0 += rr.x; v1 += rr.y;
                    }
                    *(float2*)(Cf + gr + col) = make_float2(v0, v1);
                }
            }
        }
    }
}

// ---------------- HMMA flash attention (split-bf16, fp32 softmax) -----------
// CTA = (64 q-rows, head, batch). 4 warps x 16 q-rows. K/V tiles of 64 keys.
// smem row stride 144B; double-buffered K/V hi/lo via cp.async.
#define KSTRB 144
#define FTILE (64 * KSTRB)            // 9216 bytes per tile component
#define FS_Q0   0
#define FS_STG  (2 * FTILE)           // 18432: stages start
#define FS_MASK (FS_STG + 2 * 4 * FTILE)  // 92160
#define FSMEM   (FS_MASK + 128)       // 92288

__global__ __launch_bounds__(128) void flash_tc(
    const bf16* __restrict__ qh, const bf16* __restrict__ ql,
    const unsigned char* __restrict__ smask,
    bf16* __restrict__ ohi, bf16* __restrict__ olo)
{
    extern __shared__ __align__(128) char sm[];
    uint32_t sb = cvta_s(sm);
    int qt = blockIdx.x, h = blockIdx.y, b = blockIdx.z;
    int tid = threadIdx.x, lane = tid & 31, w = tid >> 5;
    int lrow = lane & 15, lcol = (lane >> 4) << 3;
    size_t tok0 = (size_t)b * LLEN;
    int hoff = h * HD;

    // ---- load Q tile (hi+lo) : group A ----
    #pragma unroll
    for (int i = 0; i < 8; i++) {
        int slot = tid + i * 128;            // 0..1023
        int comp = slot >> 9;                // 0=hi 1=lo
        int r    = (slot >> 3) & 63;
        int seg  = slot & 7;
        const bf16* src = (comp ? ql : qh) + (tok0 + qt * 64 + r) * QKVN + hoff + seg * 8;
        cp16(sb + FS_Q0 + comp * FTILE + r * KSTRB + seg * 16, src);
    }
    asm volatile("cp.async.commit_group;");

    // ---- stage loader ----
    auto load_stage = [&](int kt, int s) {
        uint32_t base = sb + FS_STG + s * (4 * FTILE);
        int k0 = kt * 64;
        #pragma unroll
        for (int i = 0; i < 16; i++) {
            int slot = tid + i * 128;        // 0..2047
            int comp = slot >> 9;            // 0=Khi 1=Klo 2=Vhi 3=Vlo
            int r    = (slot >> 3) & 63;
            int seg  = slot & 7;
            const bf16* buf = (comp & 1) ? ql : qh;
            int coff = (comp < 2) ? DIMD : 2 * DIMD;
            const bf16* src = buf + (tok0 + k0 + r) * QKVN + coff + hoff + seg * 8;
            cp16(base + comp * FTILE + r * KSTRB + seg * 16, src);
        }
        if (tid < 4)
            cp16(sb + FS_MASK + s * 64 + tid * 16, smask + tok0 + k0 + tid * 16);
        asm volatile("cp.async.commit_group;");
    };

    load_stage(0, 0);                         // group B

    asm volatile("cp.async.wait_group 1;" ::: "memory");   // Q done
    __syncthreads();

    // ---- Q fragments (held in regs whole kernel) ----
    uint32_t qfh[4][4], qfl[4][4];
    #pragma unroll
    for (int kc = 0; kc < 4; kc++) {
        uint32_t addr = sb + FS_Q0 + (w * 16 + lrow) * KSTRB + (kc * 16 + lcol) * 2;
        ldm_x4(addr, qfh[kc][0], qfh[kc][1], qfh[kc][2], qfh[kc][3]);
        ldm_x4(addr + FTILE, qfl[kc][0], qfl[kc][1], qfl[kc][2], qfl[kc][3]);
    }

    float O[8][4];
    #pragma unroll
    for (int nt = 0; nt < 8; nt++)
        #pragma unroll
        for (int t = 0; t < 4; t++) O[nt][t] = 0.f;
    float m0r = -1e30f, m1r = -1e30f, l0r = 0.f, l1r = 0.f;

    int colb = 2 * (lane & 3);
    int qrow0 = qt * 64 + w * 16 + (lane >> 2);
    int qrow1 = qrow0 + 8;

    for (int kt = 0; kt <= qt; kt++) {
        int s = kt & 1;
        if (kt < qt) {
            load_stage(kt + 1, s ^ 1);
            asm volatile("cp.async.wait_group 1;" ::: "memory");
        } else {
            asm volatile("cp.async.wait_group 0;" ::: "memory");
        }
        __syncthreads();

        uint32_t KHB = sb + FS_STG + s * (4 * FTILE);
        uint32_t KLB = KHB + FTILE;
        uint32_t VHB = KHB + 2 * FTILE;
        uint32_t VLB = KHB + 3 * FTILE;

        // ---- S = Q K^T (3-pass split) ----
        float S[8][4];
        #pragma unroll
        for (int nt = 0; nt < 8; nt++)
            #pragma unroll
            for (int t = 0; t < 4; t++) S[nt][t] = 0.f;

        #pragma unroll
        for (int kc = 0; kc < 4; kc++) {
            uint32_t bh[8][2], bl[8][2];
            #pragma unroll
            for (int nj = 0; nj < 4; nj++) {
                uint32_t addr = KHB + (nj * 16 + lrow) * KSTRB + (kc * 16 + lcol) * 2;
                uint32_t r0, r1, r2, r3;
                ldm_x4(addr, r0, r1, r2, r3);
                bh[nj * 2][0] = r0; bh[nj * 2][1] = r2;
                bh[nj * 2 + 1][0] = r1; bh[nj * 2 + 1][1] = r3;
                ldm_x4(addr + FTILE, r0, r1, r2, r3);
                bl[nj * 2][0] = r0; bl[nj * 2][1] = r2;
                bl[nj * 2 + 1][0] = r1; bl[nj * 2 + 1][1] = r3;
            }
            #pragma unroll
            for (int nt = 0; nt < 8; nt++) {
                mma_bf16(S[nt][0], S[nt][1], S[nt][2], S[nt][3],
                         qfh[kc][0], qfh[kc][1], qfh[kc][2], qfh[kc][3],
                         bh[nt][0], bh[nt][1]);
                mma_bf16(S[nt][0], S[nt][1], S[nt][2], S[nt][3],
                         qfl[kc][0], qfl[kc][1], qfl[kc][2], qfl[kc][3],
                         bh[nt][0], bh[nt][1]);
                mma_bf16(S[nt][0], S[nt][1], S[nt][2], S[nt][3],
                         qfh[kc][0], qfh[kc][1], qfh[kc][2], qfh[kc][3],
                         bl[nt][0], bl[nt][1]);
            }
        }

        // ---- scale + mask ----
        #pragma unroll
        for (int nt = 0; nt < 8; nt++) {
            int c0 = kt * 64 + nt * 8 + colb;
            unsigned short mmsk = *(const unsigned short*)(sm + FS_MASK + s * 64 + nt * 8 + colb);
            bool k0m = (mmsk & 0xFF) != 0;
            bool k1m = (mmsk >> 8) != 0;
            float s0 = S[nt][0] * 0.125f, s1 = S[nt][1] * 0.125f;
            float s2 = S[nt][2] * 0.125f, s3 = S[nt][3] * 0.125f;
            S[nt][0] = (c0 > qrow0     || k0m) ? -10000.f : s0;
            S[nt][1] = (c0 + 1 > qrow0 || k1m) ? -10000.f : s1;
            S[nt][2] = (c0 > qrow1     || k0m) ? -10000.f : s2;
            S[nt][3] = (c0 + 1 > qrow1 || k1m) ? -10000.f : s3;
        }

        // ---- online softmax ----
        float t0 = -1e30f, t1 = -1e30f;
        #pragma unroll
        for (int nt = 0; nt < 8; nt++) {
            t0 = fmaxf(t0, fmaxf(S[nt][0], S[nt][1]));
            t1 = fmaxf(t1, fmaxf(S[nt][2], S[nt][3]));
        }
        t0 = fmaxf(t0, __shfl_xor_sync(0xFFFFFFFFu, t0, 1));
        t0 = fmaxf(t0, __shfl_xor_sync(0xFFFFFFFFu, t0, 2));
        t1 = fmaxf(t1, __shfl_xor_sync(0xFFFFFFFFu, t1, 1));
        t1 = fmaxf(t1, __shfl_xor_sync(0xFFFFFFFFu, t1, 2));
        float mn0 = fmaxf(m0r, t0), mn1 = fmaxf(m1r, t1);
        float a0 = __expf(m0r - mn0), a1 = __expf(m1r - mn1);
        m0r = mn0; m1r = mn1;

        uint32_t ph[8][2], pl[8][2];
        float ps0 = 0.f, ps1 = 0.f;
        #pragma unroll
        for (int nt = 0; nt < 8; nt++) {
            float p0 = __expf(S[nt][0] - mn0);
            float p1 = __expf(S[nt][1] - mn0);
            float p2 = __expf(S[nt][2] - mn1);
            float p3 = __expf(S[nt][3] - mn1);
            ps0 += p0 + p1; ps1 += p2 + p3;
            bf16 h0 = __float2bfloat16(p0), h1 = __float2bfloat16(p1);
            bf16 h2 = __float2bfloat16(p2), h3 = __float2bfloat16(p3);
            ph[nt][0] = pack2bf(h0, h1);
            ph[nt][1] = pack2bf(h2, h3);
            pl[nt][0] = pack2bf(__float2bfloat16(p0 - __bfloat162float(h0)),
                                __float2bfloat16(p1 - __bfloat162float(h1)));
            pl[nt][1] = pack2bf(__float2bfloat16(p2 - __bfloat162float(h2)),
                                __float2bfloat16(p3 - __bfloat162float(h3)));
        }
        ps0 += __shfl_xor_sync(0xFFFFFFFFu, ps0, 1);
        ps0 += __shfl_xor_sync(0xFFFFFFFFu, ps0, 2);
        ps1 += __shfl_xor_sync(0xFFFFFFFFu, ps1, 1);
        ps1 += __shfl_xor_sync(0xFFFFFFFFu, ps1, 2);
        l0r = l0r * a0 + ps0;
        l1r = l1r * a1 + ps1;
        #pragma unroll
        for (int nt = 0; nt < 8; nt++) {
            O[nt][0] *= a0; O[nt][1] *= a0;
            O[nt][2] *= a1; O[nt][3] *= a1;
        }

        // ---- O += P V (3-pass split) ----
        #pragma unroll
        for (int kc = 0; kc < 4; kc++) {
            uint32_t ah0 = ph[2 * kc][0], ah1 = ph[2 * kc][1];
            uint32_t ah2 = ph[2 * kc + 1][0], ah3 = ph[2 * kc + 1][1];
            uint32_t al0 = pl[2 * kc][0], al1 = pl[2 * kc][1];
            uint32_t al2 = pl[2 * kc + 1][0], al3 = pl[2 * kc + 1][1];
            #pragma unroll
            for (int dn = 0; dn < 4; dn++) {
                int g = lane >> 3, j = lane & 7;
                uint32_t addr = VHB + (kc * 16 + ((g & 1) ? 8 : 0) + j) * KSTRB
                              + (dn * 16 + ((g >> 1) ? 8 : 0)) * 2;
                uint32_t vh0, vh1, vh2, vh3, vl0, vl1, vl2, vl3;
                ldm_x4_t(addr, vh0, vh1, vh2, vh3);
                ldm_x4_t(addr + FTILE, vl0, vl1, vl2, vl3);
                int n0t = 2 * dn, n1t = 2 * dn + 1;
                mma_bf16(O[n0t][0], O[n0t][1], O[n0t][2], O[n0t][3],
                         ah0, ah1, ah2, ah3, vh0, vh1);
                mma_bf16(O[n0t][0], O[n0t][1], O[n0t][2], O[n0t][3],
                         al0, al1, al2, al3, vh0, vh1);
                mma_bf16(O[n0t][0], O[n0t][1], O[n0t][2], O[n0t][3],
                         ah0, ah1, ah2, ah3, vl0, vl1);
                mma_bf16(O[n1t][0], O[n1t][1], O[n1t][2], O[n1t][3],
                         ah0, ah1, ah2, ah3, vh2, vh3);
                mma_bf16(O[n1t][0], O[n1t][1], O[n1t][2], O[n1t][3],
                         al0, al1, al2, al3, vh2, vh3);
                mma_bf16(O[n1t][0], O[n1t][1], O[n1t][2], O[n1t][3],
                         ah0, ah1, ah2, ah3, vl2, vl3);
            }
        }
        __syncthreads();
    }

    // ---- finalize + store hi/lo ----
    float i0 = 1.f / l0r, i1 = 1.f / l1r;
    size_t t0k = tok0 + qt * 64 + w * 16 + (lane >> 2);
    size_t t1k = t0k + 8;
    #pragma unroll
    for (int nt = 0; nt < 8; nt++) {
        int col = hoff + nt * 8 + colb;
        float o0 = O[nt][0] * i0, o1 = O[nt][1] * i0;
        float o2 = O[nt][2] * i1, o3 = O[nt][3] * i1;
        bf16 h0 = __float2bfloat16(o0), h1 = __float2bfloat16(o1);
        bf16 h2 = __float2bfloat16(o2), h3 = __float2bfloat16(o3);
        *(uint32_t*)(ohi + t0k * DIMD + col) = pack2bf(h0, h1);
        *(uint32_t*)(ohi + t1k * DIMD + col) = pack2bf(h2, h3);
        *(uint32_t*)(olo + t0k * DIMD + col) =
            pack2bf(__float2bfloat16(o0 - __bfloat162float(h0)),
                    __float2bfloat16(o1 - __bfloat162float(h1)));
        *(uint32_t*)(olo + t1k * DIMD + col) =
            pack2bf(__float2bfloat16(o2 - __bfloat162float(h2)),
                    __float2bfloat16(o3 - __bfloat162float(h3)));
    }
}

// ---------------- driver -----------------------------------------------------
extern "C" void kernel_launch(void* const* d_in, const int* in_sizes, int n_in,
                              void* d_out, int out_size)
{
    const float* x          = (const float*)d_in[0];
    const unsigned char* sm = (const unsigned char*)d_in[1];
    const float* wq         = (const float*)d_in[2];
    const float* wk         = (const float*)d_in[3];
    const float* wv         = (const float*)d_in[4];
    const float* wo         = (const float*)d_in[5];
    const float* g1         = (const float*)d_in[6];
    const float* b1         = (const float*)d_in[7];
    const float* g2         = (const float*)d_in[8];
    const float* b2         = (const float*)d_in[9];
    const float* w_mlp1     = (const float*)d_in[10];
    const float* b_mlp1     = (const float*)d_in[11];
    const float* w_mlp2     = (const float*)d_in[12];
    const float* b_mlp2     = (const float*)d_in[13];
    float* out = (float*)d_out;

    bf16 *nxh, *nxl, *wqkvh, *wqkvl, *woh, *wol, *w1h, *w1l, *w2h, *w2l;
    bf16 *qkvh, *qkvl, *atth, *attl, *hh, *hl;
    float *x1;
    cudaGetSymbolAddress((void**)&nxh, g_nx_hi);   cudaGetSymbolAddress((void**)&nxl, g_nx_lo);
    cudaGetSymbolAddress((void**)&wqkvh, g_wqkv_hi); cudaGetSymbolAddress((void**)&wqkvl, g_wqkv_lo);
    cudaGetSymbolAddress((void**)&woh, g_wo_hi);   cudaGetSymbolAddress((void**)&wol, g_wo_lo);
    cudaGetSymbolAddress((void**)&w1h, g_w1_hi);   cudaGetSymbolAddress((void**)&w1l, g_w1_lo);
    cudaGetSymbolAddress((void**)&w2h, g_w2_hi);   cudaGetSymbolAddress((void**)&w2l, g_w2_lo);
    cudaGetSymbolAddress((void**)&qkvh, g_qkv_hi); cudaGetSymbolAddress((void**)&qkvl, g_qkv_lo);
    cudaGetSymbolAddress((void**)&atth, g_attn_hi); cudaGetSymbolAddress((void**)&attl, g_attn_lo);
    cudaGetSymbolAddress((void**)&x1, g_x1);
    cudaGetSymbolAddress((void**)&hh, g_h_hi);     cudaGetSymbolAddress((void**)&hl, g_h_lo);

    cudaFuncSetAttribute(gemm_tc<1>, cudaFuncAttributeMaxDynamicSharedMemorySize, SMEM_DYN);
    cudaFuncSetAttribute(gemm_tc<2>, cudaFuncAttributeMaxDynamicSharedMemorySize, SMEM_DYN);
    cudaFuncSetAttribute(gemm_tc<3>, cudaFuncAttributeMaxDynamicSharedMemorySize, SMEM_DYN);
    cudaFuncSetAttribute(gemm_tc<4>, cudaFuncAttributeMaxDynamicSharedMemorySize, SMEM_DYN);
    cudaFuncSetAttribute(flash_tc, cudaFuncAttributeMaxDynamicSharedMemorySize, FSMEM);

    dim3 blk(256);
    const int DD = DIMD * DIMD;

    convert_kernel<<<DD / 1024, blk>>>(wq, wqkvh, wqkvl, DD);
    convert_kernel<<<DD / 1024, blk>>>(wk, wqkvh + DD, wqkvl + DD, DD);
    convert_kernel<<<DD / 1024, blk>>>(wv, wqkvh + 2 * DD, wqkvl + 2 * DD, DD);
    convert_kernel<<<DD / 1024, blk>>>(wo, woh, wol, DD);
    convert_kernel<<<(FFD * DIMD) / 1024, blk>>>(w_mlp1, w1h, w1l, FFD * DIMD);
    convert_kernel<<<(DIMD * FFD) / 1024, blk>>>(w_mlp2, w2h, w2l, DIMD * FFD);

    // 1. nx = LN(x; g1,b1)
    ln_kernel<<<MTOK, blk>>>(x, g1, b1, nxh, nxl);
    // 2. qkv(hi,lo) = nx @ wqkv^T
    gemm_tc<4><<<dim3(QKVN / 128, MTOK / 128), blk, SMEM_DYN>>>(
        nxh, nxl, wqkvh, wqkvl, nullptr, nullptr, nullptr, qkvh, qkvl,
        MTOK, QKVN, DIMD);
    // 3. attn(hi,lo) = flash(qkv)
    flash_tc<<<dim3(LLEN / 64, NHEAD, BB), dim3(128), FSMEM>>>(qkvh, qkvl, sm, atth, attl);
    // 4. x1 = x + attn @ wo^T
    gemm_tc<1><<<dim3(DIMD / 128, MTOK / 128), blk, SMEM_DYN>>>(
        atth, attl, woh, wol, nullptr, x, x1, nullptr, nullptr,
        MTOK, DIMD, DIMD);
    // 5. nx = LN(x1; g2,b2)
    ln_kernel<<<MTOK, blk>>>(x1, g2, b2, nxh, nxl);
    // 6. h(hi,lo) = gelu(nx @ w1^T + b1)
    gemm_tc<3><<<dim3(FFD / 128, MTOK / 128), blk, SMEM_DYN>>>(
        nxh, nxl, w1h, w1l, b_mlp1, nullptr, nullptr, hh, hl,
        MTOK, FFD, DIMD);
    // 7. out = x1 + h @ w2^T + b2
    gemm_tc<2><<<dim3(DIMD / 128, MTOK / 128), blk, SMEM_DYN>>>(
        hh, hl, w2h, w2l, b_mlp2, x1, out, nullptr, nullptr,
        MTOK, DIMD, FFD);
}

// round 5
// speedup vs baseline: 6.4529x; 1.4134x over previous
#include <cuda_runtime.h>
#include <cuda_fp16.h>
#include <math.h>
#include <stddef.h>
#include <stdint.h>

#define DIMD 1024
#define BB 2
#define LLEN 2048
#define MTOK 4096
#define NHEAD 16
#define HD 64
#define FFD 4096
#define QKVN 3072

typedef __half f16;

// ---------------- scratch (device globals; no allocations allowed) ----------
__device__ f16  g_nx_hi[MTOK * DIMD],  g_nx_lo[MTOK * DIMD];
__device__ f16  g_wqkv_hi[QKVN * DIMD];
__device__ f16  g_wo_hi[DIMD * DIMD];
__device__ f16  g_w1_hi[FFD * DIMD];
__device__ f16  g_w2_hi[DIMD * FFD];
__device__ f16  g_qkv_hi[(size_t)MTOK * QKVN], g_qkv_lo[(size_t)MTOK * QKVN];
__device__ f16  g_attn_hi[MTOK * DIMD], g_attn_lo[MTOK * DIMD];
__device__ float g_x1[MTOK * DIMD];
__device__ f16  g_h_hi[(size_t)MTOK * FFD], g_h_lo[(size_t)MTOK * FFD];

// ---------------- helpers -----------------------------------------------------
__device__ __forceinline__ uint32_t cvta_s(const void* p) {
    return (uint32_t)__cvta_generic_to_shared(p);
}
__device__ __forceinline__ void cp16(uint32_t dst, const void* src) {
    asm volatile("cp.async.cg.shared.global [%0], [%1], 16;" :: "r"(dst), "l"(src) : "memory");
}
__device__ __forceinline__ void ldm_x4(uint32_t addr, uint32_t& r0, uint32_t& r1,
                                       uint32_t& r2, uint32_t& r3) {
    asm volatile("ldmatrix.sync.aligned.m8n8.x4.shared.b16 {%0,%1,%2,%3}, [%4];"
                 : "=r"(r0), "=r"(r1), "=r"(r2), "=r"(r3) : "r"(addr));
}
__device__ __forceinline__ void ldm_x4_t(uint32_t addr, uint32_t& r0, uint32_t& r1,
                                         uint32_t& r2, uint32_t& r3) {
    asm volatile("ldmatrix.sync.aligned.m8n8.x4.trans.shared.b16 {%0,%1,%2,%3}, [%4];"
                 : "=r"(r0), "=r"(r1), "=r"(r2), "=r"(r3) : "r"(addr));
}
__device__ __forceinline__ void mma_f16(float& d0, float& d1, float& d2, float& d3,
                                        uint32_t a0, uint32_t a1, uint32_t a2, uint32_t a3,
                                        uint32_t b0, uint32_t b1) {
    asm volatile(
        "mma.sync.aligned.m16n8k16.row.col.f32.f16.f16.f32 "
        "{%0,%1,%2,%3}, {%4,%5,%6,%7}, {%8,%9}, {%0,%1,%2,%3};"
        : "+f"(d0), "+f"(d1), "+f"(d2), "+f"(d3)
        : "r"(a0), "r"(a1), "r"(a2), "r"(a3), "r"(b0), "r"(b1));
}
__device__ __forceinline__ uint32_t pack2h(f16 a, f16 b) {
    return (uint32_t)__half_as_ushort(a) | ((uint32_t)__half_as_ushort(b) << 16);
}

// ---------------- conversion: fp32 -> hi fp16 (weights) ----------------------
__global__ __launch_bounds__(256) void convert_hi(
    const float* __restrict__ w, f16* __restrict__ hi, int n)
{
    int i = (blockIdx.x * 256 + threadIdx.x) * 4;
    if (i >= n) return;
    float4 v = *(const float4*)(w + i);
    f16 h4[4];
    h4[0] = __float2half_rn(v.x); h4[1] = __float2half_rn(v.y);
    h4[2] = __float2half_rn(v.z); h4[3] = __float2half_rn(v.w);
    *(uint2*)(hi + i) = *(uint2*)h4;
}

// ---------------- LayerNorm -> (hi, lo) fp16 ---------------------------------
__global__ __launch_bounds__(256) void ln_kernel(
    const float* __restrict__ x, const float* __restrict__ g,
    const float* __restrict__ b, f16* __restrict__ ohi, f16* __restrict__ olo)
{
    int row = blockIdx.x;
    int tid = threadIdx.x;
    float4 v = ((const float4*)(x + (size_t)row * DIMD))[tid];
    float s  = v.x + v.y + v.z + v.w;
    float sq = v.x * v.x + v.y * v.y + v.z * v.z + v.w * v.w;
    #pragma unroll
    for (int o = 16; o; o >>= 1) {
        s  += __shfl_xor_sync(0xFFFFFFFFu, s,  o);
        sq += __shfl_xor_sync(0xFFFFFFFFu, sq, o);
    }
    __shared__ float red[8], red2[8], mu_s, rs_s;
    int w = tid >> 5, ln = tid & 31;
    if (ln == 0) { red[w] = s; red2[w] = sq; }
    __syncthreads();
    if (tid == 0) {
        float ts = 0.f, tq = 0.f;
        #pragma unroll
        for (int i = 0; i < 8; i++) { ts += red[i]; tq += red2[i]; }
        float mu  = ts * (1.0f / DIMD);
        float var = tq * (1.0f / DIMD) - mu * mu;
        mu_s = mu;
        rs_s = rsqrtf(var + 1e-5f);
    }
    __syncthreads();
    float mu = mu_s, rs = rs_s;
    float4 gv = ((const float4*)g)[tid];
    float4 bv = ((const float4*)b)[tid];
    float o4[4];
    o4[0] = (v.x - mu) * rs * gv.x + bv.x;
    o4[1] = (v.y - mu) * rs * gv.y + bv.y;
    o4[2] = (v.z - mu) * rs * gv.z + bv.z;
    o4[3] = (v.w - mu) * rs * gv.w + bv.w;
    f16 h4[4], l4[4];
    #pragma unroll
    for (int j = 0; j < 4; j++) {
        f16 h = __float2half_rn(o4[j]);
        h4[j] = h;
        l4[j] = __float2half_rn(o4[j] - __half2float(h));
    }
    size_t base = (size_t)row * DIMD + tid * 4;
    *(uint2*)(ohi + base) = *(uint2*)h4;
    *(uint2*)(olo + base) = *(uint2*)l4;
}

// ---------------- HMMA 2-pass split-fp16 GEMM --------------------------------
// C = (Ahi + Alo) @ Bhi^T ; only B's fp16 rounding dropped (~1.4e-4).
// EPI: 1=f32+res  2=f32+bias+res  3=bias+gelu->(hi,lo)  4=(hi,lo; lo only col<DIMD)
#define SSTRIDE 40
#define TILE_BYTES (128 * SSTRIDE * 2)
#define STAGE_BYTES (2 * TILE_BYTES)
#define NSTAGE 3
#define SMEM_DYN (NSTAGE * STAGE_BYTES)

template <int EPI>
__global__ __launch_bounds__(256) void gemm_tc(
    const f16* __restrict__ Ahi, const f16* __restrict__ Alo,
    const f16* __restrict__ Bhi,
    const float* __restrict__ bias, const float* __restrict__ res,
    float* __restrict__ Cf, f16* __restrict__ Chi, f16* __restrict__ Clo,
    int M, int N, int K)
{
    extern __shared__ __align__(128) char smem[];
    uint32_t sbase = cvta_s(smem);
    int tid  = threadIdx.x;
    int lane = tid & 31;
    int w    = tid >> 5;
    int warpM = w & 3, warpN = w >> 2;
    int m0 = blockIdx.y * 128, n0 = blockIdx.x * 128;

    const int kcpp = K >> 5;
    const int C = 2 * kcpp;

    float acc[2][8][4];
    #pragma unroll
    for (int i = 0; i < 2; i++)
        #pragma unroll
        for (int j = 0; j < 8; j++)
            #pragma unroll
            for (int t = 0; t < 4; t++) acc[i][j][t] = 0.f;

    auto load_chunk = [&](int c, int stage) {
        int phase = (c >= kcpp);
        int k0 = (c - (phase ? kcpp : 0)) << 5;
        const f16* Ap = phase ? Alo : Ahi;
        uint32_t abuf = sbase + stage * STAGE_BYTES;
        uint32_t bbuf = abuf + TILE_BYTES;
        #pragma unroll
        for (int i = 0; i < 2; i++) {
            int idx = tid + i * 256;
            int row = idx >> 2;
            int cg  = idx & 3;
            uint32_t doff = row * (SSTRIDE * 2) + cg * 16;
            cp16(abuf + doff, Ap  + (size_t)(m0 + row) * K + k0 + cg * 8);
            cp16(bbuf + doff, Bhi + (size_t)(n0 + row) * K + k0 + cg * 8);
        }
        asm volatile("cp.async.commit_group;");
    };

    load_chunk(0, 0);
    load_chunk(1, 1);
    load_chunk(2, 2);

    int lrow = lane & 15;
    int lcol = (lane >> 4) << 3;

    for (int c = 0; c < C; c++) {
        asm volatile("cp.async.wait_group 2;" ::: "memory");
        __syncthreads();
        int stage = c - (c / NSTAGE) * NSTAGE;
        uint32_t abuf = sbase + stage * STAGE_BYTES;
        uint32_t bbuf = abuf + TILE_BYTES;

        #pragma unroll
        for (int ks = 0; ks < 2; ks++) {
            int kk = ks * 16;
            uint32_t a[2][4];
            #pragma unroll
            for (int mi = 0; mi < 2; mi++) {
                int r = warpM * 32 + mi * 16 + lrow;
                uint32_t addr = abuf + (r * SSTRIDE + kk + lcol) * 2;
                ldm_x4(addr, a[mi][0], a[mi][1], a[mi][2], a[mi][3]);
            }
            uint32_t bfr[8][2];
            #pragma unroll
            for (int nj = 0; nj < 4; nj++) {
                int r = warpN * 64 + nj * 16 + lrow;
                uint32_t addr = bbuf + (r * SSTRIDE + kk + lcol) * 2;
                uint32_t b0, b1, b2, b3;
                ldm_x4(addr, b0, b1, b2, b3);
                bfr[nj * 2 + 0][0] = b0; bfr[nj * 2 + 0][1] = b2;
                bfr[nj * 2 + 1][0] = b1; bfr[nj * 2 + 1][1] = b3;
            }
            #pragma unroll
            for (int mi = 0; mi < 2; mi++)
                #pragma unroll
                for (int nt = 0; nt < 8; nt++)
                    mma_f16(acc[mi][nt][0], acc[mi][nt][1], acc[mi][nt][2], acc[mi][nt][3],
                            a[mi][0], a[mi][1], a[mi][2], a[mi][3],
                            bfr[nt][0], bfr[nt][1]);
        }
        __syncthreads();
        if (c + NSTAGE < C) load_chunk(c + NSTAGE, stage);
    }

    int rbase = m0 + warpM * 32 + (lane >> 2);
    int cbase = n0 + warpN * 64 + (lane & 3) * 2;

    #pragma unroll
    for (int mi = 0; mi < 2; mi++) {
        #pragma unroll
        for (int half = 0; half < 2; half++) {
            int row = rbase + mi * 16 + half * 8;
            size_t gr = (size_t)row * N;
            #pragma unroll
            for (int nt = 0; nt < 8; nt++) {
                int col = cbase + nt * 8;
                float v0 = acc[mi][nt][half * 2 + 0];
                float v1 = acc[mi][nt][half * 2 + 1];
                if (EPI == 2 || EPI == 3) { v0 += bias[col]; v1 += bias[col + 1]; }
                if (EPI == 3 || EPI == 4) {
                    if (EPI == 3) {
                        v0 = 0.5f * v0 * (1.f + erff(v0 * 0.70710678118654752f));
                        v1 = 0.5f * v1 * (1.f + erff(v1 * 0.70710678118654752f));
                    }
                    f16 h0 = __float2half_rn(v0);
                    f16 h1 = __float2half_rn(v1);
                    *(uint32_t*)(Chi + gr + col) = pack2h(h0, h1);
                    if (EPI != 4 || col < DIMD) {
                        f16 l0 = __float2half_rn(v0 - __half2float(h0));
                        f16 l1 = __float2half_rn(v1 - __half2float(h1));
                        *(uint32_t*)(Clo + gr + col) = pack2h(l0, l1);
                    }
                } else {
                    float2 rr = *(const float2*)(res + gr + col);
                    v0 += rr.x; v1 += rr.y;
                    *(float2*)(Cf + gr + col) = make_float2(v0, v1);
                }
            }
        }
    }
}

// ---------------- HMMA flash attention (2-pass split-fp16) -------------------
// CTA = (64 q-rows, head, batch). 4 warps x 16 q-rows. K/V tiles of 64 keys.
// S = (Qhi+Qlo) K^T ; O = (Phi+Plo) V ; K/V in fp16-hi only.
#define KSTRB 144
#define FTILE (64 * KSTRB)                 // 9216 bytes
#define FS_Q0   0                          // Qhi, Qlo
#define FS_STG  (2 * FTILE)                // stages: 2 x (Khi, Vhi)
#define FS_MASK (FS_STG + 2 * 2 * FTILE)   // 55296
#define FSMEM   (FS_MASK + 128)

__global__ __launch_bounds__(128) void flash_tc(
    const f16* __restrict__ qh, const f16* __restrict__ ql,
    const unsigned char* __restrict__ smask,
    f16* __restrict__ ohi, f16* __restrict__ olo)
{
    extern __shared__ __align__(128) char sm[];
    uint32_t sb = cvta_s(sm);
    int qt = blockIdx.x, h = blockIdx.y, b = blockIdx.z;
    int tid = threadIdx.x, lane = tid & 31, w = tid >> 5;
    int lrow = lane & 15, lcol = (lane >> 4) << 3;
    size_t tok0 = (size_t)b * LLEN;
    int hoff = h * HD;

    // ---- load Q tile (hi+lo) ----
    #pragma unroll
    for (int i = 0; i < 8; i++) {
        int slot = tid + i * 128;            // 0..1023
        int comp = slot >> 9;                // 0=hi 1=lo
        int r    = (slot >> 3) & 63;
        int seg  = slot & 7;
        const f16* src = (comp ? ql : qh) + (tok0 + qt * 64 + r) * QKVN + hoff + seg * 8;
        cp16(sb + FS_Q0 + comp * FTILE + r * KSTRB + seg * 16, src);
    }
    asm volatile("cp.async.commit_group;");

    // ---- stage loader: Khi + Vhi ----
    auto load_stage = [&](int kt, int s) {
        uint32_t base = sb + FS_STG + s * (2 * FTILE);
        int k0 = kt * 64;
        #pragma unroll
        for (int i = 0; i < 8; i++) {
            int slot = tid + i * 128;        // 0..1023
            int comp = slot >> 9;            // 0=Khi 1=Vhi
            int r    = (slot >> 3) & 63;
            int seg  = slot & 7;
            int coff = comp ? 2 * DIMD : DIMD;
            const f16* src = qh + (tok0 + k0 + r) * QKVN + coff + hoff + seg * 8;
            cp16(base + comp * FTILE + r * KSTRB + seg * 16, src);
        }
        if (tid < 4)
            cp16(sb + FS_MASK + s * 64 + tid * 16, smask + tok0 + k0 + tid * 16);
        asm volatile("cp.async.commit_group;");
    };

    load_stage(0, 0);

    asm volatile("cp.async.wait_group 1;" ::: "memory");   // Q done
    __syncthreads();

    // ---- Q fragments (held in regs whole kernel) ----
    uint32_t qfh[4][4], qfl[4][4];
    #pragma unroll
    for (int kc = 0; kc < 4; kc++) {
        uint32_t addr = sb + FS_Q0 + (w * 16 + lrow) * KSTRB + (kc * 16 + lcol) * 2;
        ldm_x4(addr, qfh[kc][0], qfh[kc][1], qfh[kc][2], qfh[kc][3]);
        ldm_x4(addr + FTILE, qfl[kc][0], qfl[kc][1], qfl[kc][2], qfl[kc][3]);
    }

    float O[8][4];
    #pragma unroll
    for (int nt = 0; nt < 8; nt++)
        #pragma unroll
        for (int t = 0; t < 4; t++) O[nt][t] = 0.f;
    float m0r = -1e30f, m1r = -1e30f, l0r = 0.f, l1r = 0.f;

    int colb = 2 * (lane & 3);
    int qrow0 = qt * 64 + w * 16 + (lane >> 2);
    int qrow1 = qrow0 + 8;

    for (int kt = 0; kt <= qt; kt++) {
        int s = kt & 1;
        if (kt < qt) {
            load_stage(kt + 1, s ^ 1);
            asm volatile("cp.async.wait_group 1;" ::: "memory");
        } else {
            asm volatile("cp.async.wait_group 0;" ::: "memory");
        }
        __syncthreads();

        uint32_t KHB = sb + FS_STG + s * (2 * FTILE);
        uint32_t VHB = KHB + FTILE;

        // ---- S = Q K^T (2-pass) ----
        float S[8][4];
        #pragma unroll
        for (int nt = 0; nt < 8; nt++)
            #pragma unroll
            for (int t = 0; t < 4; t++) S[nt][t] = 0.f;

        #pragma unroll
        for (int kc = 0; kc < 4; kc++) {
            uint32_t bh[8][2];
            #pragma unroll
            for (int nj = 0; nj < 4; nj++) {
                uint32_t addr = KHB + (nj * 16 + lrow) * KSTRB + (kc * 16 + lcol) * 2;
                uint32_t r0, r1, r2, r3;
                ldm_x4(addr, r0, r1, r2, r3);
                bh[nj * 2][0] = r0; bh[nj * 2][1] = r2;
                bh[nj * 2 + 1][0] = r1; bh[nj * 2 + 1][1] = r3;
            }
            #pragma unroll
            for (int nt = 0; nt < 8; nt++) {
                mma_f16(S[nt][0], S[nt][1], S[nt][2], S[nt][3],
                        qfh[kc][0], qfh[kc][1], qfh[kc][2], qfh[kc][3],
                        bh[nt][0], bh[nt][1]);
                mma_f16(S[nt][0], S[nt][1], S[nt][2], S[nt][3],
                        qfl[kc][0], qfl[kc][1], qfl[kc][2], qfl[kc][3],
                        bh[nt][0], bh[nt][1]);
            }
        }

        // ---- scale + mask ----
        #pragma unroll
        for (int nt = 0; nt < 8; nt++) {
            int c0 = kt * 64 + nt * 8 + colb;
            unsigned short mmsk = *(const unsigned short*)(sm + FS_MASK + s * 64 + nt * 8 + colb);
            bool k0m = (mmsk & 0xFF) != 0;
            bool k1m = (mmsk >> 8) != 0;
            float s0 = S[nt][0] * 0.125f, s1 = S[nt][1] * 0.125f;
            float s2 = S[nt][2] * 0.125f, s3 = S[nt][3] * 0.125f;
            S[nt][0] = (c0 > qrow0     || k0m) ? -10000.f : s0;
            S[nt][1] = (c0 + 1 > qrow0 || k1m) ? -10000.f : s1;
            S[nt][2] = (c0 > qrow1     || k0m) ? -10000.f : s2;
            S[nt][3] = (c0 + 1 > qrow1 || k1m) ? -10000.f : s3;
        }

        // ---- online softmax ----
        float t0 = -1e30f, t1 = -1e30f;
        #pragma unroll
        for (int nt = 0; nt < 8; nt++) {
            t0 = fmaxf(t0, fmaxf(S[nt][0], S[nt][1]));
            t1 = fmaxf(t1, fmaxf(S[nt][2], S[nt][3]));
        }
        t0 = fmaxf(t0, __shfl_xor_sync(0xFFFFFFFFu, t0, 1));
        t0 = fmaxf(t0, __shfl_xor_sync(0xFFFFFFFFu, t0, 2));
        t1 = fmaxf(t1, __shfl_xor_sync(0xFFFFFFFFu, t1, 1));
        t1 = fmaxf(t1, __shfl_xor_sync(0xFFFFFFFFu, t1, 2));
        float mn0 = fmaxf(m0r, t0), mn1 = fmaxf(m1r, t1);
        float a0 = __expf(m0r - mn0), a1 = __expf(m1r - mn1);
        m0r = mn0; m1r = mn1;

        uint32_t ph[8][2], pl[8][2];
        float ps0 = 0.f, ps1 = 0.f;
        #pragma unroll
        for (int nt = 0; nt < 8; nt++) {
            float p0 = __expf(S[nt][0] - mn0);
            float p1 = __expf(S[nt][1] - mn0);
            float p2 = __expf(S[nt][2] - mn1);
            float p3 = __expf(S[nt][3] - mn1);
            ps0 += p0 + p1; ps1 += p2 + p3;
            f16 h0 = __float2half_rn(p0), h1 = __float2half_rn(p1);
            f16 h2 = __float2half_rn(p2), h3 = __float2half_rn(p3);
            ph[nt][0] = pack2h(h0, h1);
            ph[nt][1] = pack2h(h2, h3);
            pl[nt][0] = pack2h(__float2half_rn(p0 - __half2float(h0)),
                               __float2half_rn(p1 - __half2float(h1)));
            pl[nt][1] = pack2h(__float2half_rn(p2 - __half2float(h2)),
                               __float2half_rn(p3 - __half2float(h3)));
        }
        ps0 += __shfl_xor_sync(0xFFFFFFFFu, ps0, 1);
        ps0 += __shfl_xor_sync(0xFFFFFFFFu, ps0, 2);
        ps1 += __shfl_xor_sync(0xFFFFFFFFu, ps1, 1);
        ps1 += __shfl_xor_sync(0xFFFFFFFFu, ps1, 2);
        l0r = l0r * a0 + ps0;
        l1r = l1r * a1 + ps1;
        #pragma unroll
        for (int nt = 0; nt < 8; nt++) {
            O[nt][0] *= a0; O[nt][1] *= a0;
            O[nt][2] *= a1; O[nt][3] *= a1;
        }

        // ---- O += P V (2-pass) ----
        #pragma unroll
        for (int kc = 0; kc < 4; kc++) {
            uint32_t ah0 = ph[2 * kc][0], ah1 = ph[2 * kc][1];
            uint32_t ah2 = ph[2 * kc + 1][0], ah3 = ph[2 * kc + 1][1];
            uint32_t al0 = pl[2 * kc][0], al1 = pl[2 * kc][1];
            uint32_t al2 = pl[2 * kc + 1][0], al3 = pl[2 * kc + 1][1];
            #pragma unroll
            for (int dn = 0; dn < 4; dn++) {
                int g = lane >> 3, j = lane & 7;
                uint32_t addr = VHB + (kc * 16 + ((g & 1) ? 8 : 0) + j) * KSTRB
                              + (dn * 16 + ((g >> 1) ? 8 : 0)) * 2;
                uint32_t vh0, vh1, vh2, vh3;
                ldm_x4_t(addr, vh0, vh1, vh2, vh3);
                int n0t = 2 * dn, n1t = 2 * dn + 1;
                mma_f16(O[n0t][0], O[n0t][1], O[n0t][2], O[n0t][3],
                        ah0, ah1, ah2, ah3, vh0, vh1);
                mma_f16(O[n0t][0], O[n0t][1], O[n0t][2], O[n0t][3],
                        al0, al1, al2, al3, vh0, vh1);
                mma_f16(O[n1t][0], O[n1t][1], O[n1t][2], O[n1t][3],
                        ah0, ah1, ah2, ah3, vh2, vh3);
                mma_f16(O[n1t][0], O[n1t][1], O[n1t][2], O[n1t][3],
                        al0, al1, al2, al3, vh2, vh3);
            }
        }
        __syncthreads();
    }

    // ---- finalize + store hi/lo ----
    float i0 = 1.f / l0r, i1 = 1.f / l1r;
    size_t t0k = tok0 + qt * 64 + w * 16 + (lane >> 2);
    size_t t1k = t0k + 8;
    #pragma unroll
    for (int nt = 0; nt < 8; nt++) {
        int col = hoff + nt * 8 + colb;
        float o0 = O[nt][0] * i0, o1 = O[nt][1] * i0;
        float o2 = O[nt][2] * i1, o3 = O[nt][3] * i1;
        f16 h0 = __float2half_rn(o0), h1 = __float2half_rn(o1);
        f16 h2 = __float2half_rn(o2), h3 = __float2half_rn(o3);
        *(uint32_t*)(ohi + t0k * DIMD + col) = pack2h(h0, h1);
        *(uint32_t*)(ohi + t1k * DIMD + col) = pack2h(h2, h3);
        *(uint32_t*)(olo + t0k * DIMD + col) =
            pack2h(__float2half_rn(o0 - __half2float(h0)),
                   __float2half_rn(o1 - __half2float(h1)));
        *(uint32_t*)(olo + t1k * DIMD + col) =
            pack2h(__float2half_rn(o2 - __half2float(h2)),
                   __float2half_rn(o3 - __half2float(h3)));
    }
}

// ---------------- driver -----------------------------------------------------
extern "C" void kernel_launch(void* const* d_in, const int* in_sizes, int n_in,
                              void* d_out, int out_size)
{
    const float* x          = (const float*)d_in[0];
    const unsigned char* sm = (const unsigned char*)d_in[1];
    const float* wq         = (const float*)d_in[2];
    const float* wk         = (const float*)d_in[3];
    const float* wv         = (const float*)d_in[4];
    const float* wo         = (const float*)d_in[5];
    const float* g1         = (const float*)d_in[6];
    const float* b1         = (const float*)d_in[7];
    const float* g2         = (const float*)d_in[8];
    const float* b2         = (const float*)d_in[9];
    const float* w_mlp1     = (const float*)d_in[10];
    const float* b_mlp1     = (const float*)d_in[11];
    const float* w_mlp2     = (const float*)d_in[12];
    const float* b_mlp2     = (const float*)d_in[13];
    float* out = (float*)d_out;

    f16 *nxh, *nxl, *wqkvh, *woh, *w1h, *w2h;
    f16 *qkvh, *qkvl, *atth, *attl, *hh, *hl;
    float *x1;
    cudaGetSymbolAddress((void**)&nxh, g_nx_hi);   cudaGetSymbolAddress((void**)&nxl, g_nx_lo);
    cudaGetSymbolAddress((void**)&wqkvh, g_wqkv_hi);
    cudaGetSymbolAddress((void**)&woh, g_wo_hi);
    cudaGetSymbolAddress((void**)&w1h, g_w1_hi);
    cudaGetSymbolAddress((void**)&w2h, g_w2_hi);
    cudaGetSymbolAddress((void**)&qkvh, g_qkv_hi); cudaGetSymbolAddress((void**)&qkvl, g_qkv_lo);
    cudaGetSymbolAddress((void**)&atth, g_attn_hi); cudaGetSymbolAddress((void**)&attl, g_attn_lo);
    cudaGetSymbolAddress((void**)&x1, g_x1);
    cudaGetSymbolAddress((void**)&hh, g_h_hi);     cudaGetSymbolAddress((void**)&hl, g_h_lo);

    cudaFuncSetAttribute(gemm_tc<1>, cudaFuncAttributeMaxDynamicSharedMemorySize, SMEM_DYN);
    cudaFuncSetAttribute(gemm_tc<2>, cudaFuncAttributeMaxDynamicSharedMemorySize, SMEM_DYN);
    cudaFuncSetAttribute(gemm_tc<3>, cudaFuncAttributeMaxDynamicSharedMemorySize, SMEM_DYN);
    cudaFuncSetAttribute(gemm_tc<4>, cudaFuncAttributeMaxDynamicSharedMemorySize, SMEM_DYN);
    cudaFuncSetAttribute(flash_tc, cudaFuncAttributeMaxDynamicSharedMemorySize, FSMEM);

    dim3 blk(256);
    const int DD = DIMD * DIMD;

    convert_hi<<<DD / 1024, blk>>>(wq, wqkvh, DD);
    convert_hi<<<DD / 1024, blk>>>(wk, wqkvh + DD, DD);
    convert_hi<<<DD / 1024, blk>>>(wv, wqkvh + 2 * DD, DD);
    convert_hi<<<DD / 1024, blk>>>(wo, woh, DD);
    convert_hi<<<(FFD * DIMD) / 1024, blk>>>(w_mlp1, w1h, FFD * DIMD);
    convert_hi<<<(DIMD * FFD) / 1024, blk>>>(w_mlp2, w2h, DIMD * FFD);

    // 1. nx = LN(x; g1,b1)
    ln_kernel<<<MTOK, blk>>>(x, g1, b1, nxh, nxl);
    // 2. qkv(hi; lo for q cols) = nx @ wqkv^T
    gemm_tc<4><<<dim3(QKVN / 128, MTOK / 128), blk, SMEM_DYN>>>(
        nxh, nxl, wqkvh, nullptr, nullptr, nullptr, qkvh, qkvl,
        MTOK, QKVN, DIMD);
    // 3. attn(hi,lo) = flash(qkv)
    flash_tc<<<dim3(LLEN / 64, NHEAD, BB), dim3(128), FSMEM>>>(qkvh, qkvl, sm, atth, attl);
    // 4. x1 = x + attn @ wo^T
    gemm_tc<1><<<dim3(DIMD / 128, MTOK / 128), blk, SMEM_DYN>>>(
        atth, attl, woh, nullptr, x, x1, nullptr, nullptr,
        MTOK, DIMD, DIMD);
    // 5. nx = LN(x1; g2,b2)
    ln_kernel<<<MTOK, blk>>>(x1, g2, b2, nxh, nxl);
    // 6. h(hi,lo) = gelu(nx @ w1^T + b1)
    gemm_tc<3><<<dim3(FFD / 128, MTOK / 128), blk, SMEM_DYN>>>(
        nxh, nxl, w1h, b_mlp1, nullptr, nullptr, hh, hl,
        MTOK, FFD, DIMD);
    // 7. out = x1 + h @ w2^T + b2
    gemm_tc<2><<<dim3(DIMD / 128, MTOK / 128), blk, SMEM_DYN>>>(
        hh, hl, w2h, b_mlp2, x1, out, nullptr, nullptr,
        MTOK, DIMD, FFD);
}

// round 6
// speedup vs baseline: 11.2057x; 1.7365x over previous
#include <cuda_runtime.h>
#include <cuda_fp16.h>
#include <math.h>
#include <stddef.h>
#include <stdint.h>

#define DIMD 1024
#define BB 2
#define LLEN 2048
#define MTOK 4096
#define NHEAD 16
#define HD 64
#define FFD 4096
#define QKVN 3072

typedef __half f16;

// ---------------- scratch (device globals; no allocations allowed) ----------
__device__ f16  g_nx[MTOK * DIMD];
__device__ f16  g_wqkv[QKVN * DIMD];
__device__ f16  g_wo[DIMD * DIMD];
__device__ f16  g_w1[FFD * DIMD];
__device__ f16  g_w2[DIMD * FFD];
__device__ f16  g_qkv[(size_t)MTOK * QKVN];
__device__ f16  g_attn[MTOK * DIMD];
__device__ float g_x1[MTOK * DIMD];
__device__ f16  g_h[(size_t)MTOK * FFD];

// ---------------- helpers -----------------------------------------------------
__device__ __forceinline__ uint32_t cvta_s(const void* p) {
    return (uint32_t)__cvta_generic_to_shared(p);
}
__device__ __forceinline__ void cp16(uint32_t dst, const void* src) {
    asm volatile("cp.async.cg.shared.global [%0], [%1], 16;" :: "r"(dst), "l"(src) : "memory");
}
__device__ __forceinline__ void ldm_x4(uint32_t addr, uint32_t& r0, uint32_t& r1,
                                       uint32_t& r2, uint32_t& r3) {
    asm volatile("ldmatrix.sync.aligned.m8n8.x4.shared.b16 {%0,%1,%2,%3}, [%4];"
                 : "=r"(r0), "=r"(r1), "=r"(r2), "=r"(r3) : "r"(addr));
}
__device__ __forceinline__ void ldm_x4_t(uint32_t addr, uint32_t& r0, uint32_t& r1,
                                         uint32_t& r2, uint32_t& r3) {
    asm volatile("ldmatrix.sync.aligned.m8n8.x4.trans.shared.b16 {%0,%1,%2,%3}, [%4];"
                 : "=r"(r0), "=r"(r1), "=r"(r2), "=r"(r3) : "r"(addr));
}
__device__ __forceinline__ void mma_f16(float& d0, float& d1, float& d2, float& d3,
                                        uint32_t a0, uint32_t a1, uint32_t a2, uint32_t a3,
                                        uint32_t b0, uint32_t b1) {
    asm volatile(
        "mma.sync.aligned.m16n8k16.row.col.f32.f16.f16.f32 "
        "{%0,%1,%2,%3}, {%4,%5,%6,%7}, {%8,%9}, {%0,%1,%2,%3};"
        : "+f"(d0), "+f"(d1), "+f"(d2), "+f"(d3)
        : "r"(a0), "r"(a1), "r"(a2), "r"(a3), "r"(b0), "r"(b1));
}
__device__ __forceinline__ uint32_t pack2h(f16 a, f16 b) {
    return (uint32_t)__half_as_ushort(a) | ((uint32_t)__half_as_ushort(b) << 16);
}

// ---------------- conversion: fp32 -> fp16 -----------------------------------
__global__ __launch_bounds__(256) void convert_hi(
    const float* __restrict__ w, f16* __restrict__ hi, int n)
{
    int i = (blockIdx.x * 256 + threadIdx.x) * 4;
    if (i >= n) return;
    float4 v = *(const float4*)(w + i);
    f16 h4[4];
    h4[0] = __float2half_rn(v.x); h4[1] = __float2half_rn(v.y);
    h4[2] = __float2half_rn(v.z); h4[3] = __float2half_rn(v.w);
    *(uint2*)(hi + i) = *(uint2*)h4;
}

// ---------------- LayerNorm -> fp16 ------------------------------------------
__global__ __launch_bounds__(256) void ln_kernel(
    const float* __restrict__ x, const float* __restrict__ g,
    const float* __restrict__ b, f16* __restrict__ ohi)
{
    int row = blockIdx.x;
    int tid = threadIdx.x;
    float4 v = ((const float4*)(x + (size_t)row * DIMD))[tid];
    float s  = v.x + v.y + v.z + v.w;
    float sq = v.x * v.x + v.y * v.y + v.z * v.z + v.w * v.w;
    #pragma unroll
    for (int o = 16; o; o >>= 1) {
        s  += __shfl_xor_sync(0xFFFFFFFFu, s,  o);
        sq += __shfl_xor_sync(0xFFFFFFFFu, sq, o);
    }
    __shared__ float red[8], red2[8], mu_s, rs_s;
    int w = tid >> 5, ln = tid & 31;
    if (ln == 0) { red[w] = s; red2[w] = sq; }
    __syncthreads();
    if (tid == 0) {
        float ts = 0.f, tq = 0.f;
        #pragma unroll
        for (int i = 0; i < 8; i++) { ts += red[i]; tq += red2[i]; }
        float mu  = ts * (1.0f / DIMD);
        float var = tq * (1.0f / DIMD) - mu * mu;
        mu_s = mu;
        rs_s = rsqrtf(var + 1e-5f);
    }
    __syncthreads();
    float mu = mu_s, rs = rs_s;
    float4 gv = ((const float4*)g)[tid];
    float4 bv = ((const float4*)b)[tid];
    f16 h4[4];
    h4[0] = __float2half_rn((v.x - mu) * rs * gv.x + bv.x);
    h4[1] = __float2half_rn((v.y - mu) * rs * gv.y + bv.y);
    h4[2] = __float2half_rn((v.z - mu) * rs * gv.z + bv.z);
    h4[3] = __float2half_rn((v.w - mu) * rs * gv.w + bv.w);
    *(uint2*)(ohi + (size_t)row * DIMD + tid * 4) = *(uint2*)h4;
}

// ---------------- HMMA fp16 GEMM (single pass, fp32 accum) -------------------
// EPI: 1=f32+res  2=f32+bias+res  3=bias+gelu->f16  4=f16
#define SSTRIDE 40
#define TILE_BYTES (128 * SSTRIDE * 2)
#define STAGE_BYTES (2 * TILE_BYTES)
#define NSTAGE 3
#define SMEM_DYN (NSTAGE * STAGE_BYTES)

template <int EPI>
__global__ __launch_bounds__(256) void gemm_tc(
    const f16* __restrict__ A, const f16* __restrict__ B,
    const float* __restrict__ bias, const float* __restrict__ res,
    float* __restrict__ Cf, f16* __restrict__ Ch,
    int M, int N, int K)
{
    extern __shared__ __align__(128) char smem[];
    uint32_t sbase = cvta_s(smem);
    int tid  = threadIdx.x;
    int lane = tid & 31;
    int w    = tid >> 5;
    int warpM = w & 3, warpN = w >> 2;
    int m0 = blockIdx.y * 128, n0 = blockIdx.x * 128;

    const int C = K >> 5;

    float acc[2][8][4];
    #pragma unroll
    for (int i = 0; i < 2; i++)
        #pragma unroll
        for (int j = 0; j < 8; j++)
            #pragma unroll
            for (int t = 0; t < 4; t++) acc[i][j][t] = 0.f;

    auto load_chunk = [&](int c, int stage) {
        int k0 = c << 5;
        uint32_t abuf = sbase + stage * STAGE_BYTES;
        uint32_t bbuf = abuf + TILE_BYTES;
        #pragma unroll
        for (int i = 0; i < 2; i++) {
            int idx = tid + i * 256;
            int row = idx >> 2;
            int cg  = idx & 3;
            uint32_t doff = row * (SSTRIDE * 2) + cg * 16;
            cp16(abuf + doff, A + (size_t)(m0 + row) * K + k0 + cg * 8);
            cp16(bbuf + doff, B + (size_t)(n0 + row) * K + k0 + cg * 8);
        }
        asm volatile("cp.async.commit_group;");
    };

    load_chunk(0, 0);
    load_chunk(1, 1);
    load_chunk(2, 2);

    int lrow = lane & 15;
    int lcol = (lane >> 4) << 3;

    for (int c = 0; c < C; c++) {
        asm volatile("cp.async.wait_group 2;" ::: "memory");
        __syncthreads();
        int stage = c - (c / NSTAGE) * NSTAGE;
        uint32_t abuf = sbase + stage * STAGE_BYTES;
        uint32_t bbuf = abuf + TILE_BYTES;

        #pragma unroll
        for (int ks = 0; ks < 2; ks++) {
            int kk = ks * 16;
            uint32_t a[2][4];
            #pragma unroll
            for (int mi = 0; mi < 2; mi++) {
                int r = warpM * 32 + mi * 16 + lrow;
                uint32_t addr = abuf + (r * SSTRIDE + kk + lcol) * 2;
                ldm_x4(addr, a[mi][0], a[mi][1], a[mi][2], a[mi][3]);
            }
            uint32_t bfr[8][2];
            #pragma unroll
            for (int nj = 0; nj < 4; nj++) {
                int r = warpN * 64 + nj * 16 + lrow;
                uint32_t addr = bbuf + (r * SSTRIDE + kk + lcol) * 2;
                uint32_t b0, b1, b2, b3;
                ldm_x4(addr, b0, b1, b2, b3);
                bfr[nj * 2 + 0][0] = b0; bfr[nj * 2 + 0][1] = b2;
                bfr[nj * 2 + 1][0] = b1; bfr[nj * 2 + 1][1] = b3;
            }
            #pragma unroll
            for (int mi = 0; mi < 2; mi++)
                #pragma unroll
                for (int nt = 0; nt < 8; nt++)
                    mma_f16(acc[mi][nt][0], acc[mi][nt][1], acc[mi][nt][2], acc[mi][nt][3],
                            a[mi][0], a[mi][1], a[mi][2], a[mi][3],
                            bfr[nt][0], bfr[nt][1]);
        }
        __syncthreads();
        if (c + NSTAGE < C) load_chunk(c + NSTAGE, stage);
    }

    int rbase = m0 + warpM * 32 + (lane >> 2);
    int cbase = n0 + warpN * 64 + (lane & 3) * 2;

    #pragma unroll
    for (int mi = 0; mi < 2; mi++) {
        #pragma unroll
        for (int half = 0; half < 2; half++) {
            int row = rbase + mi * 16 + half * 8;
            size_t gr = (size_t)row * N;
            #pragma unroll
            for (int nt = 0; nt < 8; nt++) {
                int col = cbase + nt * 8;
                float v0 = acc[mi][nt][half * 2 + 0];
                float v1 = acc[mi][nt][half * 2 + 1];
                if (EPI == 2 || EPI == 3) { v0 += bias[col]; v1 += bias[col + 1]; }
                if (EPI == 3 || EPI == 4) {
                    if (EPI == 3) {
                        v0 = 0.5f * v0 * (1.f + erff(v0 * 0.70710678118654752f));
                        v1 = 0.5f * v1 * (1.f + erff(v1 * 0.70710678118654752f));
                    }
                    *(uint32_t*)(Ch + gr + col) =
                        pack2h(__float2half_rn(v0), __float2half_rn(v1));
                } else {
                    float2 rr = *(const float2*)(res + gr + col);
                    v0 += rr.x; v1 += rr.y;
                    *(float2*)(Cf + gr + col) = make_float2(v0, v1);
                }
            }
        }
    }
}

// ---------------- HMMA flash attention (fp16, fp32 softmax) ------------------
// CTA = (64 q-rows, head, batch). 4 warps x 16 q-rows. K/V tiles of 64 keys.
#define KSTRB 144
#define FTILE (64 * KSTRB)                 // 9216 bytes
#define FS_Q0   0                          // Q tile
#define FS_STG  FTILE                      // stages: 2 x (K, V)
#define FS_MASK (FS_STG + 2 * 2 * FTILE)   // 46080
#define FSMEM   (FS_MASK + 128)

__global__ __launch_bounds__(128) void flash_tc(
    const f16* __restrict__ qkv, const unsigned char* __restrict__ smask,
    f16* __restrict__ oh)
{
    extern __shared__ __align__(128) char sm[];
    uint32_t sb = cvta_s(sm);
    int qt = blockIdx.x, h = blockIdx.y, b = blockIdx.z;
    int tid = threadIdx.x, lane = tid & 31, w = tid >> 5;
    int lrow = lane & 15, lcol = (lane >> 4) << 3;
    size_t tok0 = (size_t)b * LLEN;
    int hoff = h * HD;

    // ---- load Q tile ----
    #pragma unroll
    for (int i = 0; i < 4; i++) {
        int slot = tid + i * 128;            // 0..511
        int r    = slot >> 3;
        int seg  = slot & 7;
        const f16* src = qkv + (tok0 + qt * 64 + r) * QKVN + hoff + seg * 8;
        cp16(sb + FS_Q0 + r * KSTRB + seg * 16, src);
    }
    asm volatile("cp.async.commit_group;");

    // ---- stage loader: K + V ----
    auto load_stage = [&](int kt, int s) {
        uint32_t base = sb + FS_STG + s * (2 * FTILE);
        int k0 = kt * 64;
        #pragma unroll
        for (int i = 0; i < 8; i++) {
            int slot = tid + i * 128;        // 0..1023
            int comp = slot >> 9;            // 0=K 1=V
            int r    = (slot >> 3) & 63;
            int seg  = slot & 7;
            int coff = comp ? 2 * DIMD : DIMD;
            const f16* src = qkv + (tok0 + k0 + r) * QKVN + coff + hoff + seg * 8;
            cp16(base + comp * FTILE + r * KSTRB + seg * 16, src);
        }
        if (tid < 4)
            cp16(sb + FS_MASK + s * 64 + tid * 16, smask + tok0 + k0 + tid * 16);
        asm volatile("cp.async.commit_group;");
    };

    load_stage(0, 0);

    asm volatile("cp.async.wait_group 1;" ::: "memory");   // Q done
    __syncthreads();

    // ---- Q fragments ----
    uint32_t qf[4][4];
    #pragma unroll
    for (int kc = 0; kc < 4; kc++) {
        uint32_t addr = sb + FS_Q0 + (w * 16 + lrow) * KSTRB + (kc * 16 + lcol) * 2;
        ldm_x4(addr, qf[kc][0], qf[kc][1], qf[kc][2], qf[kc][3]);
    }

    float O[8][4];
    #pragma unroll
    for (int nt = 0; nt < 8; nt++)
        #pragma unroll
        for (int t = 0; t < 4; t++) O[nt][t] = 0.f;
    float m0r = -1e30f, m1r = -1e30f, l0r = 0.f, l1r = 0.f;

    int colb = 2 * (lane & 3);
    int qrow0 = qt * 64 + w * 16 + (lane >> 2);
    int qrow1 = qrow0 + 8;

    for (int kt = 0; kt <= qt; kt++) {
        int s = kt & 1;
        if (kt < qt) {
            load_stage(kt + 1, s ^ 1);
            asm volatile("cp.async.wait_group 1;" ::: "memory");
        } else {
            asm volatile("cp.async.wait_group 0;" ::: "memory");
        }
        __syncthreads();

        uint32_t KHB = sb + FS_STG + s * (2 * FTILE);
        uint32_t VHB = KHB + FTILE;

        // ---- S = Q K^T ----
        float S[8][4];
        #pragma unroll
        for (int nt = 0; nt < 8; nt++)
            #pragma unroll
            for (int t = 0; t < 4; t++) S[nt][t] = 0.f;

        #pragma unroll
        for (int kc = 0; kc < 4; kc++) {
            uint32_t bh[8][2];
            #pragma unroll
            for (int nj = 0; nj < 4; nj++) {
                uint32_t addr = KHB + (nj * 16 + lrow) * KSTRB + (kc * 16 + lcol) * 2;
                uint32_t r0, r1, r2, r3;
                ldm_x4(addr, r0, r1, r2, r3);
                bh[nj * 2][0] = r0; bh[nj * 2][1] = r2;
                bh[nj * 2 + 1][0] = r1; bh[nj * 2 + 1][1] = r3;
            }
            #pragma unroll
            for (int nt = 0; nt < 8; nt++)
                mma_f16(S[nt][0], S[nt][1], S[nt][2], S[nt][3],
                        qf[kc][0], qf[kc][1], qf[kc][2], qf[kc][3],
                        bh[nt][0], bh[nt][1]);
        }

        // ---- scale + mask ----
        #pragma unroll
        for (int nt = 0; nt < 8; nt++) {
            int c0 = kt * 64 + nt * 8 + colb;
            unsigned short mmsk = *(const unsigned short*)(sm + FS_MASK + s * 64 + nt * 8 + colb);
            bool k0m = (mmsk & 0xFF) != 0;
            bool k1m = (mmsk >> 8) != 0;
            float s0 = S[nt][0] * 0.125f, s1 = S[nt][1] * 0.125f;
            float s2 = S[nt][2] * 0.125f, s3 = S[nt][3] * 0.125f;
            S[nt][0] = (c0 > qrow0     || k0m) ? -10000.f : s0;
            S[nt][1] = (c0 + 1 > qrow0 || k1m) ? -10000.f : s1;
            S[nt][2] = (c0 > qrow1     || k0m) ? -10000.f : s2;
            S[nt][3] = (c0 + 1 > qrow1 || k1m) ? -10000.f : s3;
        }

        // ---- online softmax ----
        float t0 = -1e30f, t1 = -1e30f;
        #pragma unroll
        for (int nt = 0; nt < 8; nt++) {
            t0 = fmaxf(t0, fmaxf(S[nt][0], S[nt][1]));
            t1 = fmaxf(t1, fmaxf(S[nt][2], S[nt][3]));
        }
        t0 = fmaxf(t0, __shfl_xor_sync(0xFFFFFFFFu, t0, 1));
        t0 = fmaxf(t0, __shfl_xor_sync(0xFFFFFFFFu, t0, 2));
        t1 = fmaxf(t1, __shfl_xor_sync(0xFFFFFFFFu, t1, 1));
        t1 = fmaxf(t1, __shfl_xor_sync(0xFFFFFFFFu, t1, 2));
        float mn0 = fmaxf(m0r, t0), mn1 = fmaxf(m1r, t1);
        float a0 = __expf(m0r - mn0), a1 = __expf(m1r - mn1);
        m0r = mn0; m1r = mn1;

        uint32_t ph[8][2];
        float ps0 = 0.f, ps1 = 0.f;
        #pragma unroll
        for (int nt = 0; nt < 8; nt++) {
            float p0 = __expf(S[nt][0] - mn0);
            float p1 = __expf(S[nt][1] - mn0);
            float p2 = __expf(S[nt][2] - mn1);
            float p3 = __expf(S[nt][3] - mn1);
            ps0 += p0 + p1; ps1 += p2 + p3;
            ph[nt][0] = pack2h(__float2half_rn(p0), __float2half_rn(p1));
            ph[nt][1] = pack2h(__float2half_rn(p2), __float2half_rn(p3));
        }
        ps0 += __shfl_xor_sync(0xFFFFFFFFu, ps0, 1);
        ps0 += __shfl_xor_sync(0xFFFFFFFFu, ps0, 2);
        ps1 += __shfl_xor_sync(0xFFFFFFFFu, ps1, 1);
        ps1 += __shfl_xor_sync(0xFFFFFFFFu, ps1, 2);
        l0r = l0r * a0 + ps0;
        l1r = l1r * a1 + ps1;
        #pragma unroll
        for (int nt = 0; nt < 8; nt++) {
            O[nt][0] *= a0; O[nt][1] *= a0;
            O[nt][2] *= a1; O[nt][3] *= a1;
        }

        // ---- O += P V ----
        #pragma unroll
        for (int kc = 0; kc < 4; kc++) {
            uint32_t ah0 = ph[2 * kc][0], ah1 = ph[2 * kc][1];
            uint32_t ah2 = ph[2 * kc + 1][0], ah3 = ph[2 * kc + 1][1];
            #pragma unroll
            for (int dn = 0; dn < 4; dn++) {
                int g = lane >> 3, j = lane & 7;
                uint32_t addr = VHB + (kc * 16 + ((g & 1) ? 8 : 0) + j) * KSTRB
                              + (dn * 16 + ((g >> 1) ? 8 : 0)) * 2;
                uint32_t vh0, vh1, vh2, vh3;
                ldm_x4_t(addr, vh0, vh1, vh2, vh3);
                mma_f16(O[2 * dn][0], O[2 * dn][1], O[2 * dn][2], O[2 * dn][3],
                        ah0, ah1, ah2, ah3, vh0, vh1);
                mma_f16(O[2 * dn + 1][0], O[2 * dn + 1][1], O[2 * dn + 1][2], O[2 * dn + 1][3],
                        ah0, ah1, ah2, ah3, vh2, vh3);
            }
        }
        __syncthreads();
    }

    // ---- finalize + store ----
    float i0 = 1.f / l0r, i1 = 1.f / l1r;
    size_t t0k = tok0 + qt * 64 + w * 16 + (lane >> 2);
    size_t t1k = t0k + 8;
    #pragma unroll
    for (int nt = 0; nt < 8; nt++) {
        int col = hoff + nt * 8 + colb;
        *(uint32_t*)(oh + t0k * DIMD + col) =
            pack2h(__float2half_rn(O[nt][0] * i0), __float2half_rn(O[nt][1] * i0));
        *(uint32_t*)(oh + t1k * DIMD + col) =
            pack2h(__float2half_rn(O[nt][2] * i1), __float2half_rn(O[nt][3] * i1));
    }
}

// ---------------- driver -----------------------------------------------------
extern "C" void kernel_launch(void* const* d_in, const int* in_sizes, int n_in,
                              void* d_out, int out_size)
{
    const float* x          = (const float*)d_in[0];
    const unsigned char* sm = (const unsigned char*)d_in[1];
    const float* wq         = (const float*)d_in[2];
    const float* wk         = (const float*)d_in[3];
    const float* wv         = (const float*)d_in[4];
    const float* wo         = (const float*)d_in[5];
    const float* g1         = (const float*)d_in[6];
    const float* b1         = (const float*)d_in[7];
    const float* g2         = (const float*)d_in[8];
    const float* b2         = (const float*)d_in[9];
    const float* w_mlp1     = (const float*)d_in[10];
    const float* b_mlp1     = (const float*)d_in[11];
    const float* w_mlp2     = (const float*)d_in[12];
    const float* b_mlp2     = (const float*)d_in[13];
    float* out = (float*)d_out;

    f16 *nx, *wqkv, *wo16, *w1, *w2, *qkv, *attn, *hb;
    float *x1;
    cudaGetSymbolAddress((void**)&nx, g_nx);
    cudaGetSymbolAddress((void**)&wqkv, g_wqkv);
    cudaGetSymbolAddress((void**)&wo16, g_wo);
    cudaGetSymbolAddress((void**)&w1, g_w1);
    cudaGetSymbolAddress((void**)&w2, g_w2);
    cudaGetSymbolAddress((void**)&qkv, g_qkv);
    cudaGetSymbolAddress((void**)&attn, g_attn);
    cudaGetSymbolAddress((void**)&x1, g_x1);
    cudaGetSymbolAddress((void**)&hb, g_h);

    cudaFuncSetAttribute(gemm_tc<1>, cudaFuncAttributeMaxDynamicSharedMemorySize, SMEM_DYN);
    cudaFuncSetAttribute(gemm_tc<2>, cudaFuncAttributeMaxDynamicSharedMemorySize, SMEM_DYN);
    cudaFuncSetAttribute(gemm_tc<3>, cudaFuncAttributeMaxDynamicSharedMemorySize, SMEM_DYN);
    cudaFuncSetAttribute(gemm_tc<4>, cudaFuncAttributeMaxDynamicSharedMemorySize, SMEM_DYN);
    cudaFuncSetAttribute(flash_tc, cudaFuncAttributeMaxDynamicSharedMemorySize, FSMEM);

    dim3 blk(256);
    const int DD = DIMD * DIMD;

    convert_hi<<<DD / 1024, blk>>>(wq, wqkv, DD);
    convert_hi<<<DD / 1024, blk>>>(wk, wqkv + DD, DD);
    convert_hi<<<DD / 1024, blk>>>(wv, wqkv + 2 * DD, DD);
    convert_hi<<<DD / 1024, blk>>>(wo, wo16, DD);
    convert_hi<<<(FFD * DIMD) / 1024, blk>>>(w_mlp1, w1, FFD * DIMD);
    convert_hi<<<(DIMD * FFD) / 1024, blk>>>(w_mlp2, w2, DIMD * FFD);

    // 1. nx = LN(x; g1,b1)
    ln_kernel<<<MTOK, blk>>>(x, g1, b1, nx);
    // 2. qkv = nx @ wqkv^T
    gemm_tc<4><<<dim3(QKVN / 128, MTOK / 128), blk, SMEM_DYN>>>(
        nx, wqkv, nullptr, nullptr, nullptr, qkv, MTOK, QKVN, DIMD);
    // 3. attn = flash(qkv)
    flash_tc<<<dim3(LLEN / 64, NHEAD, BB), dim3(128), FSMEM>>>(qkv, sm, attn);
    // 4. x1 = x + attn @ wo^T
    gemm_tc<1><<<dim3(DIMD / 128, MTOK / 128), blk, SMEM_DYN>>>(
        attn, wo16, nullptr, x, x1, nullptr, MTOK, DIMD, DIMD);
    // 5. nx = LN(x1; g2,b2)
    ln_kernel<<<MTOK, blk>>>(x1, g2, b2, nx);
    // 6. h = gelu(nx @ w1^T + b1)
    gemm_tc<3><<<dim3(FFD / 128, MTOK / 128), blk, SMEM_DYN>>>(
        nx, w1, b_mlp1, nullptr, nullptr, hb, MTOK, FFD, DIMD);
    // 7. out = x1 + h @ w2^T + b2
    gemm_tc<2><<<dim3(DIMD / 128, MTOK / 128), blk, SMEM_DYN>>>(
        hb, w2, b_mlp2, x1, out, nullptr, MTOK, DIMD, FFD);
}

// round 7
// speedup vs baseline: 12.6109x; 1.1254x over previous
#include <cuda_runtime.h>
#include <cuda_fp16.h>
#include <math.h>
#include <stddef.h>
#include <stdint.h>

#define DIMD 1024
#define BB 2
#define LLEN 2048
#define MTOK 4096
#define NHEAD 16
#define HD 64
#define FFD 4096
#define QKVN 3072

typedef __half f16;

// ---------------- scratch (device globals; no allocations allowed) ----------
__device__ f16  g_nx[MTOK * DIMD];
__device__ f16  g_wqkv[QKVN * DIMD];
__device__ f16  g_wo[DIMD * DIMD];
__device__ f16  g_w1[FFD * DIMD];
__device__ f16  g_w2[DIMD * FFD];
__device__ f16  g_qkv[(size_t)MTOK * QKVN];
__device__ f16  g_attn[MTOK * DIMD];
__device__ float g_x1[MTOK * DIMD];
__device__ f16  g_h[(size_t)MTOK * FFD];

// ---------------- helpers -----------------------------------------------------
__device__ __forceinline__ uint32_t cvta_s(const void* p) {
    return (uint32_t)__cvta_generic_to_shared(p);
}
__device__ __forceinline__ void cp16(uint32_t dst, const void* src) {
    asm volatile("cp.async.cg.shared.global [%0], [%1], 16;" :: "r"(dst), "l"(src) : "memory");
}
__device__ __forceinline__ void ldm_x4(uint32_t addr, uint32_t& r0, uint32_t& r1,
                                       uint32_t& r2, uint32_t& r3) {
    asm volatile("ldmatrix.sync.aligned.m8n8.x4.shared.b16 {%0,%1,%2,%3}, [%4];"
                 : "=r"(r0), "=r"(r1), "=r"(r2), "=r"(r3) : "r"(addr));
}
__device__ __forceinline__ void ldm_x4_t(uint32_t addr, uint32_t& r0, uint32_t& r1,
                                         uint32_t& r2, uint32_t& r3) {
    asm volatile("ldmatrix.sync.aligned.m8n8.x4.trans.shared.b16 {%0,%1,%2,%3}, [%4];"
                 : "=r"(r0), "=r"(r1), "=r"(r2), "=r"(r3) : "r"(addr));
}
__device__ __forceinline__ void mma_f16(float& d0, float& d1, float& d2, float& d3,
                                        uint32_t a0, uint32_t a1, uint32_t a2, uint32_t a3,
                                        uint32_t b0, uint32_t b1) {
    asm volatile(
        "mma.sync.aligned.m16n8k16.row.col.f32.f16.f16.f32 "
        "{%0,%1,%2,%3}, {%4,%5,%6,%7}, {%8,%9}, {%0,%1,%2,%3};"
        : "+f"(d0), "+f"(d1), "+f"(d2), "+f"(d3)
        : "r"(a0), "r"(a1), "r"(a2), "r"(a3), "r"(b0), "r"(b1));
}
__device__ __forceinline__ uint32_t pack2h(f16 a, f16 b) {
    return (uint32_t)__half_as_ushort(a) | ((uint32_t)__half_as_ushort(b) << 16);
}

// ---------------- merged weight conversion (1 launch) ------------------------
// segments in 1024-elem blocks: wq[0,1024) wk[1024,2048) wv[2048,3072)
// wo[3072,4096) w1[4096,8192) w2[8192,12288)
__global__ __launch_bounds__(256) void convert_all(
    const float* __restrict__ wq, const float* __restrict__ wk,
    const float* __restrict__ wv, const float* __restrict__ wo,
    const float* __restrict__ w1, const float* __restrict__ w2,
    f16* __restrict__ dqkv, f16* __restrict__ dwo,
    f16* __restrict__ dw1, f16* __restrict__ dw2)
{
    int blk = blockIdx.x;
    const float* src;
    f16* dst;
    size_t off;
    const size_t DD = (size_t)DIMD * DIMD;
    if (blk < 1024)      { src = wq; dst = dqkv;          off = (size_t)blk * 1024; }
    else if (blk < 2048) { src = wk; dst = dqkv + DD;     off = (size_t)(blk - 1024) * 1024; }
    else if (blk < 3072) { src = wv; dst = dqkv + 2 * DD; off = (size_t)(blk - 2048) * 1024; }
    else if (blk < 4096) { src = wo; dst = dwo;           off = (size_t)(blk - 3072) * 1024; }
    else if (blk < 8192) { src = w1; dst = dw1;           off = (size_t)(blk - 4096) * 1024; }
    else                 { src = w2; dst = dw2;           off = (size_t)(blk - 8192) * 1024; }
    size_t i = off + threadIdx.x * 4;
    float4 v = *(const float4*)(src + i);
    f16 h4[4];
    h4[0] = __float2half_rn(v.x); h4[1] = __float2half_rn(v.y);
    h4[2] = __float2half_rn(v.z); h4[3] = __float2half_rn(v.w);
    *(uint2*)(dst + i) = *(uint2*)h4;
}

// ---------------- LayerNorm -> fp16 ------------------------------------------
__global__ __launch_bounds__(256) void ln_kernel(
    const float* __restrict__ x, const float* __restrict__ g,
    const float* __restrict__ b, f16* __restrict__ ohi)
{
    int row = blockIdx.x;
    int tid = threadIdx.x;
    float4 v = ((const float4*)(x + (size_t)row * DIMD))[tid];
    float s  = v.x + v.y + v.z + v.w;
    float sq = v.x * v.x + v.y * v.y + v.z * v.z + v.w * v.w;
    #pragma unroll
    for (int o = 16; o; o >>= 1) {
        s  += __shfl_xor_sync(0xFFFFFFFFu, s,  o);
        sq += __shfl_xor_sync(0xFFFFFFFFu, sq, o);
    }
    __shared__ float red[8], red2[8], mu_s, rs_s;
    int w = tid >> 5, ln = tid & 31;
    if (ln == 0) { red[w] = s; red2[w] = sq; }
    __syncthreads();
    if (tid == 0) {
        float ts = 0.f, tq = 0.f;
        #pragma unroll
        for (int i = 0; i < 8; i++) { ts += red[i]; tq += red2[i]; }
        float mu  = ts * (1.0f / DIMD);
        float var = tq * (1.0f / DIMD) - mu * mu;
        mu_s = mu;
        rs_s = rsqrtf(var + 1e-5f);
    }
    __syncthreads();
    float mu = mu_s, rs = rs_s;
    float4 gv = ((const float4*)g)[tid];
    float4 bv = ((const float4*)b)[tid];
    f16 h4[4];
    h4[0] = __float2half_rn((v.x - mu) * rs * gv.x + bv.x);
    h4[1] = __float2half_rn((v.y - mu) * rs * gv.y + bv.y);
    h4[2] = __float2half_rn((v.z - mu) * rs * gv.z + bv.z);
    h4[3] = __float2half_rn((v.w - mu) * rs * gv.w + bv.w);
    *(uint2*)(ohi + (size_t)row * DIMD + tid * 4) = *(uint2*)h4;
}

// ---------------- HMMA fp16 GEMM (BK=64, fp32 accum) -------------------------
// EPI: 1=f32+res  2=f32+bias+res  3=bias+gelu->f16  4=f16
#define SSTRIDE 72                          // 64 + 8 pad (elements)
#define TILE_BYTES (128 * SSTRIDE * 2)      // 18432
#define STAGE_BYTES (2 * TILE_BYTES)        // 36864
#define NSTAGE 3
#define SMEM_DYN (NSTAGE * STAGE_BYTES)     // 110592

template <int EPI>
__global__ __launch_bounds__(256) void gemm_tc(
    const f16* __restrict__ A, const f16* __restrict__ B,
    const float* __restrict__ bias, const float* __restrict__ res,
    float* __restrict__ Cf, f16* __restrict__ Ch,
    int M, int N, int K)
{
    extern __shared__ __align__(128) char smem[];
    uint32_t sbase = cvta_s(smem);
    int tid  = threadIdx.x;
    int lane = tid & 31;
    int w    = tid >> 5;
    int warpM = w & 3, warpN = w >> 2;
    int m0 = blockIdx.y * 128, n0 = blockIdx.x * 128;

    const int C = K >> 6;                   // 64-wide chunks

    float acc[2][8][4];
    #pragma unroll
    for (int i = 0; i < 2; i++)
        #pragma unroll
        for (int j = 0; j < 8; j++)
            #pragma unroll
            for (int t = 0; t < 4; t++) acc[i][j][t] = 0.f;

    auto load_chunk = [&](int c, int stage) {
        int k0 = c << 6;
        uint32_t abuf = sbase + stage * STAGE_BYTES;
        uint32_t bbuf = abuf + TILE_BYTES;
        #pragma unroll
        for (int i = 0; i < 4; i++) {
            int idx = tid + i * 256;        // 0..1023
            int row = idx >> 3;             // 0..127
            int cg  = idx & 7;              // 16B group (8 per 128B row)
            uint32_t doff = row * (SSTRIDE * 2) + cg * 16;
            cp16(abuf + doff, A + (size_t)(m0 + row) * K + k0 + cg * 8);
            cp16(bbuf + doff, B + (size_t)(n0 + row) * K + k0 + cg * 8);
        }
        asm volatile("cp.async.commit_group;");
    };

    load_chunk(0, 0);
    load_chunk(1, 1);
    load_chunk(2, 2);

    int lrow = lane & 15;
    int lcol = (lane >> 4) << 3;

    for (int c = 0; c < C; c++) {
        asm volatile("cp.async.wait_group 2;" ::: "memory");
        __syncthreads();
        int stage = c - (c / NSTAGE) * NSTAGE;
        uint32_t abuf = sbase + stage * STAGE_BYTES;
        uint32_t bbuf = abuf + TILE_BYTES;

        #pragma unroll
        for (int ks = 0; ks < 4; ks++) {
            int kk = ks * 16;
            uint32_t a[2][4];
            #pragma unroll
            for (int mi = 0; mi < 2; mi++) {
                int r = warpM * 32 + mi * 16 + lrow;
                uint32_t addr = abuf + (r * SSTRIDE + kk + lcol) * 2;
                ldm_x4(addr, a[mi][0], a[mi][1], a[mi][2], a[mi][3]);
            }
            uint32_t bfr[8][2];
            #pragma unroll
            for (int nj = 0; nj < 4; nj++) {
                int r = warpN * 64 + nj * 16 + lrow;
                uint32_t addr = bbuf + (r * SSTRIDE + kk + lcol) * 2;
                uint32_t b0, b1, b2, b3;
                ldm_x4(addr, b0, b1, b2, b3);
                bfr[nj * 2 + 0][0] = b0; bfr[nj * 2 + 0][1] = b2;
                bfr[nj * 2 + 1][0] = b1; bfr[nj * 2 + 1][1] = b3;
            }
            #pragma unroll
            for (int mi = 0; mi < 2; mi++)
                #pragma unroll
                for (int nt = 0; nt < 8; nt++)
                    mma_f16(acc[mi][nt][0], acc[mi][nt][1], acc[mi][nt][2], acc[mi][nt][3],
                            a[mi][0], a[mi][1], a[mi][2], a[mi][3],
                            bfr[nt][0], bfr[nt][1]);
        }
        __syncthreads();
        if (c + NSTAGE < C) load_chunk(c + NSTAGE, stage);
    }

    int rbase = m0 + warpM * 32 + (lane >> 2);
    int cbase = n0 + warpN * 64 + (lane & 3) * 2;

    #pragma unroll
    for (int mi = 0; mi < 2; mi++) {
        #pragma unroll
        for (int half = 0; half < 2; half++) {
            int row = rbase + mi * 16 + half * 8;
            size_t gr = (size_t)row * N;
            #pragma unroll
            for (int nt = 0; nt < 8; nt++) {
                int col = cbase + nt * 8;
                float v0 = acc[mi][nt][half * 2 + 0];
                float v1 = acc[mi][nt][half * 2 + 1];
                if (EPI == 2 || EPI == 3) { v0 += bias[col]; v1 += bias[col + 1]; }
                if (EPI == 3 || EPI == 4) {
                    if (EPI == 3) {
                        v0 = 0.5f * v0 * (1.f + erff(v0 * 0.70710678118654752f));
                        v1 = 0.5f * v1 * (1.f + erff(v1 * 0.70710678118654752f));
                    }
                    *(uint32_t*)(Ch + gr + col) =
                        pack2h(__float2half_rn(v0), __float2half_rn(v1));
                } else {
                    float2 rr = *(const float2*)(res + gr + col);
                    v0 += rr.x; v1 += rr.y;
                    *(float2*)(Cf + gr + col) = make_float2(v0, v1);
                }
            }
        }
    }
}

// ---------------- HMMA flash attention (fp16, fp32 softmax) ------------------
#define KSTRB 144
#define FTILE (64 * KSTRB)                 // 9216 bytes
#define FS_Q0   0
#define FS_STG  FTILE
#define FS_MASK (FS_STG + 2 * 2 * FTILE)   // 46080
#define FSMEM   (FS_MASK + 128)

__global__ __launch_bounds__(128) void flash_tc(
    const f16* __restrict__ qkv, const unsigned char* __restrict__ smask,
    f16* __restrict__ oh)
{
    extern __shared__ __align__(128) char sm[];
    uint32_t sb = cvta_s(sm);
    int qt = blockIdx.x, h = blockIdx.y, b = blockIdx.z;
    int tid = threadIdx.x, lane = tid & 31, w = tid >> 5;
    int lrow = lane & 15, lcol = (lane >> 4) << 3;
    size_t tok0 = (size_t)b * LLEN;
    int hoff = h * HD;

    #pragma unroll
    for (int i = 0; i < 4; i++) {
        int slot = tid + i * 128;
        int r    = slot >> 3;
        int seg  = slot & 7;
        const f16* src = qkv + (tok0 + qt * 64 + r) * QKVN + hoff + seg * 8;
        cp16(sb + FS_Q0 + r * KSTRB + seg * 16, src);
    }
    asm volatile("cp.async.commit_group;");

    auto load_stage = [&](int kt, int s) {
        uint32_t base = sb + FS_STG + s * (2 * FTILE);
        int k0 = kt * 64;
        #pragma unroll
        for (int i = 0; i < 8; i++) {
            int slot = tid + i * 128;
            int comp = slot >> 9;
            int r    = (slot >> 3) & 63;
            int seg  = slot & 7;
            int coff = comp ? 2 * DIMD : DIMD;
            const f16* src = qkv + (tok0 + k0 + r) * QKVN + coff + hoff + seg * 8;
            cp16(base + comp * FTILE + r * KSTRB + seg * 16, src);
        }
        if (tid < 4)
            cp16(sb + FS_MASK + s * 64 + tid * 16, smask + tok0 + k0 + tid * 16);
        asm volatile("cp.async.commit_group;");
    };

    load_stage(0, 0);

    asm volatile("cp.async.wait_group 1;" ::: "memory");
    __syncthreads();

    uint32_t qf[4][4];
    #pragma unroll
    for (int kc = 0; kc < 4; kc++) {
        uint32_t addr = sb + FS_Q0 + (w * 16 + lrow) * KSTRB + (kc * 16 + lcol) * 2;
        ldm_x4(addr, qf[kc][0], qf[kc][1], qf[kc][2], qf[kc][3]);
    }

    float O[8][4];
    #pragma unroll
    for (int nt = 0; nt < 8; nt++)
        #pragma unroll
        for (int t = 0; t < 4; t++) O[nt][t] = 0.f;
    float m0r = -1e30f, m1r = -1e30f, l0r = 0.f, l1r = 0.f;

    int colb = 2 * (lane & 3);
    int qrow0 = qt * 64 + w * 16 + (lane >> 2);
    int qrow1 = qrow0 + 8;

    for (int kt = 0; kt <= qt; kt++) {
        int s = kt & 1;
        if (kt < qt) {
            load_stage(kt + 1, s ^ 1);
            asm volatile("cp.async.wait_group 1;" ::: "memory");
        } else {
            asm volatile("cp.async.wait_group 0;" ::: "memory");
        }
        __syncthreads();

        uint32_t KHB = sb + FS_STG + s * (2 * FTILE);
        uint32_t VHB = KHB + FTILE;

        float S[8][4];
        #pragma unroll
        for (int nt = 0; nt < 8; nt++)
            #pragma unroll
            for (int t = 0; t < 4; t++) S[nt][t] = 0.f;

        #pragma unroll
        for (int kc = 0; kc < 4; kc++) {
            uint32_t bh[8][2];
            #pragma unroll
            for (int nj = 0; nj < 4; nj++) {
                uint32_t addr = KHB + (nj * 16 + lrow) * KSTRB + (kc * 16 + lcol) * 2;
                uint32_t r0, r1, r2, r3;
                ldm_x4(addr, r0, r1, r2, r3);
                bh[nj * 2][0] = r0; bh[nj * 2][1] = r2;
                bh[nj * 2 + 1][0] = r1; bh[nj * 2 + 1][1] = r3;
            }
            #pragma unroll
            for (int nt = 0; nt < 8; nt++)
                mma_f16(S[nt][0], S[nt][1], S[nt][2], S[nt][3],
                        qf[kc][0], qf[kc][1], qf[kc][2], qf[kc][3],
                        bh[nt][0], bh[nt][1]);
        }

        #pragma unroll
        for (int nt = 0; nt < 8; nt++) {
            int c0 = kt * 64 + nt * 8 + colb;
            unsigned short mmsk = *(const unsigned short*)(sm + FS_MASK + s * 64 + nt * 8 + colb);
            bool k0m = (mmsk & 0xFF) != 0;
            bool k1m = (mmsk >> 8) != 0;
            float s0 = S[nt][0] * 0.125f, s1 = S[nt][1] * 0.125f;
            float s2 = S[nt][2] * 0.125f, s3 = S[nt][3] * 0.125f;
            S[nt][0] = (c0 > qrow0     || k0m) ? -10000.f : s0;
            S[nt][1] = (c0 + 1 > qrow0 || k1m) ? -10000.f : s1;
            S[nt][2] = (c0 > qrow1     || k0m) ? -10000.f : s2;
            S[nt][3] = (c0 + 1 > qrow1 || k1m) ? -10000.f : s3;
        }

        float t0 = -1e30f, t1 = -1e30f;
        #pragma unroll
        for (int nt = 0; nt < 8; nt++) {
            t0 = fmaxf(t0, fmaxf(S[nt][0], S[nt][1]));
            t1 = fmaxf(t1, fmaxf(S[nt][2], S[nt][3]));
        }
        t0 = fmaxf(t0, __shfl_xor_sync(0xFFFFFFFFu, t0, 1));
        t0 = fmaxf(t0, __shfl_xor_sync(0xFFFFFFFFu, t0, 2));
        t1 = fmaxf(t1, __shfl_xor_sync(0xFFFFFFFFu, t1, 1));
        t1 = fmaxf(t1, __shfl_xor_sync(0xFFFFFFFFu, t1, 2));
        float mn0 = fmaxf(m0r, t0), mn1 = fmaxf(m1r, t1);
        float a0 = __expf(m0r - mn0), a1 = __expf(m1r - mn1);
        m0r = mn0; m1r = mn1;

        uint32_t ph[8][2];
        float ps0 = 0.f, ps1 = 0.f;
        #pragma unroll
        for (int nt = 0; nt < 8; nt++) {
            float p0 = __expf(S[nt][0] - mn0);
            float p1 = __expf(S[nt][1] - mn0);
            float p2 = __expf(S[nt][2] - mn1);
            float p3 = __expf(S[nt][3] - mn1);
            ps0 += p0 + p1; ps1 += p2 + p3;
            ph[nt][0] = pack2h(__float2half_rn(p0), __float2half_rn(p1));
            ph[nt][1] = pack2h(__float2half_rn(p2), __float2half_rn(p3));
        }
        ps0 += __shfl_xor_sync(0xFFFFFFFFu, ps0, 1);
        ps0 += __shfl_xor_sync(0xFFFFFFFFu, ps0, 2);
        ps1 += __shfl_xor_sync(0xFFFFFFFFu, ps1, 1);
        ps1 += __shfl_xor_sync(0xFFFFFFFFu, ps1, 2);
        l0r = l0r * a0 + ps0;
        l1r = l1r * a1 + ps1;
        #pragma unroll
        for (int nt = 0; nt < 8; nt++) {
            O[nt][0] *= a0; O[nt][1] *= a0;
            O[nt][2] *= a1; O[nt][3] *= a1;
        }

        #pragma unroll
        for (int kc = 0; kc < 4; kc++) {
            uint32_t ah0 = ph[2 * kc][0], ah1 = ph[2 * kc][1];
            uint32_t ah2 = ph[2 * kc + 1][0], ah3 = ph[2 * kc + 1][1];
            #pragma unroll
            for (int dn = 0; dn < 4; dn++) {
                int g = lane >> 3, j = lane & 7;
                uint32_t addr = VHB + (kc * 16 + ((g & 1) ? 8 : 0) + j) * KSTRB
                              + (dn * 16 + ((g >> 1) ? 8 : 0)) * 2;
                uint32_t vh0, vh1, vh2, vh3;
                ldm_x4_t(addr, vh0, vh1, vh2, vh3);
                mma_f16(O[2 * dn][0], O[2 * dn][1], O[2 * dn][2], O[2 * dn][3],
                        ah0, ah1, ah2, ah3, vh0, vh1);
                mma_f16(O[2 * dn + 1][0], O[2 * dn + 1][1], O[2 * dn + 1][2], O[2 * dn + 1][3],
                        ah0, ah1, ah2, ah3, vh2, vh3);
            }
        }
        __syncthreads();
    }

    float i0 = 1.f / l0r, i1 = 1.f / l1r;
    size_t t0k = tok0 + qt * 64 + w * 16 + (lane >> 2);
    size_t t1k = t0k + 8;
    #pragma unroll
    for (int nt = 0; nt < 8; nt++) {
        int col = hoff + nt * 8 + colb;
        *(uint32_t*)(oh + t0k * DIMD + col) =
            pack2h(__float2half_rn(O[nt][0] * i0), __float2half_rn(O[nt][1] * i0));
        *(uint32_t*)(oh + t1k * DIMD + col) =
            pack2h(__float2half_rn(O[nt][2] * i1), __float2half_rn(O[nt][3] * i1));
    }
}

// ---------------- driver -----------------------------------------------------
extern "C" void kernel_launch(void* const* d_in, const int* in_sizes, int n_in,
                              void* d_out, int out_size)
{
    const float* x          = (const float*)d_in[0];
    const unsigned char* sm = (const unsigned char*)d_in[1];
    const float* wq         = (const float*)d_in[2];
    const float* wk         = (const float*)d_in[3];
    const float* wv         = (const float*)d_in[4];
    const float* wo         = (const float*)d_in[5];
    const float* g1         = (const float*)d_in[6];
    const float* b1         = (const float*)d_in[7];
    const float* g2         = (const float*)d_in[8];
    const float* b2         = (const float*)d_in[9];
    const float* w_mlp1     = (const float*)d_in[10];
    const float* b_mlp1     = (const float*)d_in[11];
    const float* w_mlp2     = (const float*)d_in[12];
    const float* b_mlp2     = (const float*)d_in[13];
    float* out = (float*)d_out;

    f16 *nx, *wqkv, *wo16, *w1, *w2, *qkv, *attn, *hb;
    float *x1;
    cudaGetSymbolAddress((void**)&nx, g_nx);
    cudaGetSymbolAddress((void**)&wqkv, g_wqkv);
    cudaGetSymbolAddress((void**)&wo16, g_wo);
    cudaGetSymbolAddress((void**)&w1, g_w1);
    cudaGetSymbolAddress((void**)&w2, g_w2);
    cudaGetSymbolAddress((void**)&qkv, g_qkv);
    cudaGetSymbolAddress((void**)&attn, g_attn);
    cudaGetSymbolAddress((void**)&x1, g_x1);
    cudaGetSymbolAddress((void**)&hb, g_h);

    cudaFuncSetAttribute(gemm_tc<1>, cudaFuncAttributeMaxDynamicSharedMemorySize, SMEM_DYN);
    cudaFuncSetAttribute(gemm_tc<2>, cudaFuncAttributeMaxDynamicSharedMemorySize, SMEM_DYN);
    cudaFuncSetAttribute(gemm_tc<3>, cudaFuncAttributeMaxDynamicSharedMemorySize, SMEM_DYN);
    cudaFuncSetAttribute(gemm_tc<4>, cudaFuncAttributeMaxDynamicSharedMemorySize, SMEM_DYN);
    cudaFuncSetAttribute(flash_tc, cudaFuncAttributeMaxDynamicSharedMemorySize, FSMEM);

    dim3 blk(256);

    // one merged weight-convert launch
    convert_all<<<12288, blk>>>(wq, wk, wv, wo, w_mlp1, w_mlp2, wqkv, wo16, w1, w2);

    // 1. nx = LN(x; g1,b1)
    ln_kernel<<<MTOK, blk>>>(x, g1, b1, nx);
    // 2. qkv = nx @ wqkv^T
    gemm_tc<4><<<dim3(QKVN / 128, MTOK / 128), blk, SMEM_DYN>>>(
        nx, wqkv, nullptr, nullptr, nullptr, qkv, MTOK, QKVN, DIMD);
    // 3. attn = flash(qkv)
    flash_tc<<<dim3(LLEN / 64, NHEAD, BB), dim3(128), FSMEM>>>(qkv, sm, attn);
    // 4. x1 = x + attn @ wo^T
    gemm_tc<1><<<dim3(DIMD / 128, MTOK / 128), blk, SMEM_DYN>>>(
        attn, wo16, nullptr, x, x1, nullptr, MTOK, DIMD, DIMD);
    // 5. nx = LN(x1; g2,b2)
    ln_kernel<<<MTOK, blk>>>(x1, g2, b2, nx);
    // 6. h = gelu(nx @ w1^T + b1)
    gemm_tc<3><<<dim3(FFD / 128, MTOK / 128), blk, SMEM_DYN>>>(
        nx, w1, b_mlp1, nullptr, nullptr, hb, MTOK, FFD, DIMD);
    // 7. out = x1 + h @ w2^T + b2
    gemm_tc<2><<<dim3(DIMD / 128, MTOK / 128), blk, SMEM_DYN>>>(
        hb, w2, b_mlp2, x1, out, nullptr, MTOK, DIMD, FFD);
}